// round 2
// baseline (speedup 1.0000x reference)
#include <cuda_runtime.h>

#define NMAX 100000
#define EMAX 1600000
#define LN_EPS 1e-5f

// ---------------- scratch (device globals: no allocation allowed) ----------
__device__ int   g_deg[NMAX];
__device__ int   g_rowstart[NMAX + 1];
__device__ int   g_cursor[NMAX];
__device__ int   g_csr_src[EMAX];
__device__ float g_buf_a[(size_t)NMAX * 128];
__device__ float g_buf_b[(size_t)NMAX * 128];

// ---------------- CSR build ------------------------------------------------
__global__ void k_zero_deg(int n) {
    int i = blockIdx.x * blockDim.x + threadIdx.x;
    if (i < n) g_deg[i] = 0;
}

__global__ void k_count(const int* __restrict__ tgt, int e) {
    int i = blockIdx.x * blockDim.x + threadIdx.x;
    if (i < e) atomicAdd(&g_deg[tgt[i]], 1);
}

// single-block exclusive scan over degrees -> rowstart, cursor
__global__ void k_scan(int n) {
    __shared__ int sums[1024];
    int t = threadIdx.x;
    int C = (n + 1023) >> 10;
    int s = t * C;
    int epos = min(n, s + C);
    int acc = 0;
    for (int i = s; i < epos; i++) acc += g_deg[i];
    sums[t] = acc;
    __syncthreads();
    for (int off = 1; off < 1024; off <<= 1) {
        int v = (t >= off) ? sums[t - off] : 0;
        __syncthreads();
        sums[t] += v;
        __syncthreads();
    }
    int run = sums[t] - acc;  // exclusive prefix
    for (int i = s; i < epos; i++) {
        g_rowstart[i] = run;
        g_cursor[i]   = run;
        run += g_deg[i];
    }
    if (s < n && epos == n) g_rowstart[n] = run;
}

__global__ void k_fill(const int* __restrict__ src, const int* __restrict__ tgt, int e) {
    int i = blockIdx.x * blockDim.x + threadIdx.x;
    if (i < e) {
        int t = tgt[i];
        int pos = atomicAdd(&g_cursor[t], 1);
        g_csr_src[pos] = src[i];
    }
}

// ---------------- GEMM K=11 (input layer): warp per node -------------------
__global__ void k_gemm0(const float* __restrict__ X, const float* __restrict__ W,
                        const float* __restrict__ b, float* __restrict__ Y, int n) {
    __shared__ float sW[11 * 128];
    __shared__ float sb[128];
    int tid = threadIdx.x;
    for (int i = tid; i < 11 * 128; i += 256) sW[i] = W[i];
    if (tid < 128) sb[tid] = b[tid];
    __syncthreads();
    int warp = tid >> 5, lane = tid & 31;
    int node = blockIdx.x * 8 + warp;
    if (node >= n) return;
    float f[11];
#pragma unroll
    for (int k = 0; k < 11; k++) f[k] = X[node * 11 + k];
    int c0 = lane * 4;
    float a0 = sb[c0], a1 = sb[c0 + 1], a2 = sb[c0 + 2], a3 = sb[c0 + 3];
#pragma unroll
    for (int k = 0; k < 11; k++) {
        a0 += f[k] * sW[(c0 + 0) * 11 + k];
        a1 += f[k] * sW[(c0 + 1) * 11 + k];
        a2 += f[k] * sW[(c0 + 2) * 11 + k];
        a3 += f[k] * sW[(c0 + 3) * 11 + k];
    }
    float4 r = make_float4(a0, a1, a2, a3);
    *(float4*)&Y[node * 128 + c0] = r;
}

// ---------------- tiled GEMM: Y[n][NT] = X[n][128] * W[NT][128]^T + b ------
// block: 256 threads, tile 128 rows x NT cols, thread tile 8 x (NT/16)
template <int NT>
__global__ void __launch_bounds__(256) k_gemm(const float* __restrict__ X,
                                              const float* __restrict__ W,
                                              const float* __restrict__ bias,
                                              float* __restrict__ Y, int n) {
    const int NG = NT / 64;  // float4 col-groups per thread (2 for 128, 1 for 64)
    __shared__ float s_x[128][33];      // [row][k-chunk], padded
    __shared__ float s_w[32][NT + 4];   // [k][col], transposed, padded
    int tid = threadIdx.x;
    int tx = tid & 15, ty = tid >> 4;
    int mBase = blockIdx.x * 128;
    float acc[8][NG * 4];
#pragma unroll
    for (int i = 0; i < 8; i++)
#pragma unroll
        for (int j = 0; j < NG * 4; j++) acc[i][j] = 0.f;

    for (int kc = 0; kc < 128; kc += 32) {
        // load X tile: 128 rows x 32 k = 1024 float4-slots over 256 threads
#pragma unroll
        for (int it = 0; it < 4; it++) {
            int idx = tid + it * 256;
            int r = idx >> 3, q = idx & 7;
            int gm = mBase + r;
            float4 v = make_float4(0.f, 0.f, 0.f, 0.f);
            if (gm < n) v = *(const float4*)&X[gm * 128 + kc + q * 4];
            s_x[r][q * 4 + 0] = v.x;
            s_x[r][q * 4 + 1] = v.y;
            s_x[r][q * 4 + 2] = v.z;
            s_x[r][q * 4 + 3] = v.w;
        }
        // load W tile transposed: NT rows x 32 k
#pragma unroll
        for (int it = 0; it < NT / 32; it++) {
            int idx = tid + it * 256;
            int c = idx >> 3, q = idx & 7;
            float4 w = *(const float4*)&W[c * 128 + kc + q * 4];
            s_w[q * 4 + 0][c] = w.x;
            s_w[q * 4 + 1][c] = w.y;
            s_w[q * 4 + 2][c] = w.z;
            s_w[q * 4 + 3][c] = w.w;
        }
        __syncthreads();
#pragma unroll
        for (int k = 0; k < 32; k++) {
            float a[8];
#pragma unroll
            for (int i = 0; i < 8; i++) a[i] = s_x[ty * 8 + i][k];
#pragma unroll
            for (int g = 0; g < NG; g++) {
                float4 w = *(float4*)&s_w[k][g * 64 + tx * 4];
#pragma unroll
                for (int i = 0; i < 8; i++) {
                    acc[i][g * 4 + 0] += a[i] * w.x;
                    acc[i][g * 4 + 1] += a[i] * w.y;
                    acc[i][g * 4 + 2] += a[i] * w.z;
                    acc[i][g * 4 + 3] += a[i] * w.w;
                }
            }
        }
        __syncthreads();
    }
#pragma unroll
    for (int i = 0; i < 8; i++) {
        int m = mBase + ty * 8 + i;
        if (m < n) {
#pragma unroll
            for (int g = 0; g < NG; g++) {
                int c0 = g * 64 + tx * 4;
                float4 r;
                r.x = acc[i][g * 4 + 0] + bias[c0 + 0];
                r.y = acc[i][g * 4 + 1] + bias[c0 + 1];
                r.z = acc[i][g * 4 + 2] + bias[c0 + 2];
                r.w = acc[i][g * 4 + 3] + bias[c0 + 3];
                *(float4*)&Y[m * NT + c0] = r;
            }
        }
    }
}

// ---------------- fused aggregate + degree-norm + LayerNorm (+ReLU) --------
__device__ __forceinline__ float warp_sum(float v) {
#pragma unroll
    for (int o = 16; o; o >>= 1) v += __shfl_xor_sync(0xffffffffu, v, o);
    return v;
}

template <int HD, bool RELU>
__global__ void k_agg_ln(const float* __restrict__ XT, const float* __restrict__ gam,
                         const float* __restrict__ bet, float* __restrict__ Y, int n) {
    int gw = (blockIdx.x * blockDim.x + threadIdx.x) >> 5;
    int lane = threadIdx.x & 31;
    if (gw >= n) return;
    int rs = g_rowstart[gw], re = g_rowstart[gw + 1];
    const int V = HD / 32;  // 4 or 2 floats per lane
    float acc[V];
#pragma unroll
    for (int i = 0; i < V; i++) acc[i] = 0.f;

    int e = rs;
    if constexpr (V == 4) {
        for (; e + 1 < re; e += 2) {
            int s0 = g_csr_src[e], s1 = g_csr_src[e + 1];
            float4 v0 = *(const float4*)&XT[s0 * HD + lane * 4];
            float4 v1 = *(const float4*)&XT[s1 * HD + lane * 4];
            acc[0] += v0.x + v1.x;
            acc[1] += v0.y + v1.y;
            acc[2] += v0.z + v1.z;
            acc[3] += v0.w + v1.w;
        }
        if (e < re) {
            int s0 = g_csr_src[e];
            float4 v0 = *(const float4*)&XT[s0 * HD + lane * 4];
            acc[0] += v0.x; acc[1] += v0.y; acc[2] += v0.z; acc[3] += v0.w;
        }
    } else {
        for (; e + 1 < re; e += 2) {
            int s0 = g_csr_src[e], s1 = g_csr_src[e + 1];
            float2 v0 = *(const float2*)&XT[s0 * HD + lane * 2];
            float2 v1 = *(const float2*)&XT[s1 * HD + lane * 2];
            acc[0] += v0.x + v1.x;
            acc[1] += v0.y + v1.y;
        }
        if (e < re) {
            int s0 = g_csr_src[e];
            float2 v0 = *(const float2*)&XT[s0 * HD + lane * 2];
            acc[0] += v0.x; acc[1] += v0.y;
        }
    }

    int deg = re - rs;
    float inv = 1.0f / (float)(deg > 0 ? deg : 1);
    float v[V];
    float psum = 0.f;
#pragma unroll
    for (int i = 0; i < V; i++) { v[i] = acc[i] * inv; psum += v[i]; }
    float mean = warp_sum(psum) * (1.0f / (float)HD);
    float d[V];
    float ps2 = 0.f;
#pragma unroll
    for (int i = 0; i < V; i++) { d[i] = v[i] - mean; ps2 += d[i] * d[i]; }
    float var = warp_sum(ps2) * (1.0f / (float)HD);
    float rstd = rsqrtf(var + LN_EPS);

    if constexpr (V == 4) {
        float4 G = *(const float4*)&gam[lane * 4];
        float4 B = *(const float4*)&bet[lane * 4];
        float4 r;
        r.x = d[0] * rstd * G.x + B.x;
        r.y = d[1] * rstd * G.y + B.y;
        r.z = d[2] * rstd * G.z + B.z;
        r.w = d[3] * rstd * G.w + B.w;
        if (RELU) {
            r.x = fmaxf(r.x, 0.f); r.y = fmaxf(r.y, 0.f);
            r.z = fmaxf(r.z, 0.f); r.w = fmaxf(r.w, 0.f);
        }
        *(float4*)&Y[gw * HD + lane * 4] = r;
    } else {
        float2 G = *(const float2*)&gam[lane * 2];
        float2 B = *(const float2*)&bet[lane * 2];
        float2 r;
        r.x = d[0] * rstd * G.x + B.x;
        r.y = d[1] * rstd * G.y + B.y;
        if (RELU) { r.x = fmaxf(r.x, 0.f); r.y = fmaxf(r.y, 0.f); }
        *(float2*)&Y[gw * HD + lane * 2] = r;
    }
}

// ---------------- launcher -------------------------------------------------
extern "C" void kernel_launch(void* const* d_in, const int* in_sizes, int n_in,
                              void* d_out, int out_size) {
    const float* nf  = (const float*)d_in[0];
    const int*   ei  = (const int*)d_in[1];
    const float* W0  = (const float*)d_in[2];
    const float* b0  = (const float*)d_in[3];
    const float* W1  = (const float*)d_in[4];
    const float* b1  = (const float*)d_in[5];
    const float* W2  = (const float*)d_in[6];
    const float* b2  = (const float*)d_in[7];
    const float* g0  = (const float*)d_in[8];
    const float* be0 = (const float*)d_in[9];
    const float* g1  = (const float*)d_in[10];
    const float* be1 = (const float*)d_in[11];
    const float* g2  = (const float*)d_in[12];
    const float* be2 = (const float*)d_in[13];

    int n = in_sizes[0] / 11;
    int e = in_sizes[1] / 2;
    const int* src = ei;
    const int* tgt = ei + e;

    float *bufA, *bufB;
    cudaGetSymbolAddress((void**)&bufA, g_buf_a);
    cudaGetSymbolAddress((void**)&bufB, g_buf_b);

    // CSR build (pull-style aggregation, no float atomics)
    k_zero_deg<<<(n + 255) / 256, 256>>>(n);
    k_count<<<(e + 255) / 256, 256>>>(tgt, e);
    k_scan<<<1, 1024>>>(n);
    k_fill<<<(e + 255) / 256, 256>>>(src, tgt, e);

    // layer 0: 11 -> 128
    k_gemm0<<<(n + 7) / 8, 256>>>(nf, W0, b0, bufA, n);
    k_agg_ln<128, true><<<(n + 7) / 8, 256>>>(bufA, g0, be0, bufB, n);

    // layer 1: 128 -> 128
    k_gemm<128><<<(n + 127) / 128, 256>>>(bufB, W1, b1, bufA, n);
    k_agg_ln<128, true><<<(n + 7) / 8, 256>>>(bufA, g1, be1, bufB, n);

    // layer 2: 128 -> 64
    k_gemm<64><<<(n + 127) / 128, 256>>>(bufB, W2, b2, bufA, n);
    k_agg_ln<64, false><<<(n + 7) / 8, 256>>>(bufA, g2, be2, (float*)d_out, n);
}

// round 4
// speedup vs baseline: 1.0495x; 1.0495x over previous
#include <cuda_runtime.h>

#define NMAX 100000
#define EMAX 1600000
#define LN_EPS 1e-5f

// ---------------- scratch (device globals: no allocation allowed) ----------
__device__ int   g_deg[NMAX];
__device__ int   g_rowstart[NMAX + 1];
__device__ int   g_cursor[NMAX];
__device__ int   g_csr_src[EMAX];
__device__ float g_buf_a[(size_t)NMAX * 128];
__device__ float g_buf_b[(size_t)NMAX * 128];

// ---------------- packed fp32x2 FMA (sm_103a) ------------------------------
__device__ __forceinline__ void ffma2(unsigned long long& d, unsigned long long a,
                                      unsigned long long b) {
    asm("fma.rn.f32x2 %0, %1, %2, %0;" : "+l"(d) : "l"(a), "l"(b));
}
__device__ __forceinline__ void unpack2(float& lo, float& hi, unsigned long long v) {
    asm("mov.b64 {%0,%1}, %2;" : "=f"(lo), "=f"(hi) : "l"(v));
}
struct __align__(16) u64x2 { unsigned long long lo, hi; };

// ---------------- CSR build ------------------------------------------------
__global__ void k_zero_deg(int n) {
    int i = blockIdx.x * blockDim.x + threadIdx.x;
    if (i < n) g_deg[i] = 0;
}

__global__ void k_count(const int* __restrict__ tgt, int e) {
    int i = blockIdx.x * blockDim.x + threadIdx.x;
    if (i < e) atomicAdd(&g_deg[tgt[i]], 1);
}

__global__ void k_scan(int n) {
    __shared__ int sums[1024];
    int t = threadIdx.x;
    int C = (n + 1023) >> 10;
    int s = t * C;
    int epos = min(n, s + C);
    int acc = 0;
    for (int i = s; i < epos; i++) acc += g_deg[i];
    sums[t] = acc;
    __syncthreads();
    for (int off = 1; off < 1024; off <<= 1) {
        int v = (t >= off) ? sums[t - off] : 0;
        __syncthreads();
        sums[t] += v;
        __syncthreads();
    }
    int run = sums[t] - acc;
    for (int i = s; i < epos; i++) {
        g_rowstart[i] = run;
        g_cursor[i]   = run;
        run += g_deg[i];
    }
    if (s < n && epos == n) g_rowstart[n] = run;
}

__global__ void k_fill(const int* __restrict__ src, const int* __restrict__ tgt, int e) {
    int i = blockIdx.x * blockDim.x + threadIdx.x;
    if (i < e) {
        int t = tgt[i];
        int pos = atomicAdd(&g_cursor[t], 1);
        g_csr_src[pos] = src[i];
    }
}

// ---------------- layer-0: aggregate RAW 11-wide features ------------------
// 16 threads per node; lane f accumulates feature f.
__global__ void k_agg_feat(const float* __restrict__ X, float* __restrict__ out, int n) {
    int g = threadIdx.x >> 4, f = threadIdx.x & 15;
    int node = blockIdx.x * 16 + g;
    if (node >= n) return;
    int rs = g_rowstart[node], re = g_rowstart[node + 1];
    float acc = 0.f;
    for (int base = rs; base < re; base += 16) {
        int idx = base + f;
        int s = (idx < re) ? g_csr_src[idx] : 0;
#pragma unroll
        for (int j = 0; j < 16; j++) {
            int sj = __shfl_sync(0xffffffffu, s, j, 16);
            if (base + j < re && f < 11) acc += X[sj * 11 + f];
        }
    }
    float inv = 1.0f / (float)max(re - rs, 1);
    if (f < 11) out[node * 11 + f] = acc * inv;
}

__device__ __forceinline__ float warp_sum(float v) {
#pragma unroll
    for (int o = 16; o; o >>= 1) v += __shfl_xor_sync(0xffffffffu, v, o);
    return v;
}

// ---------------- fused 11->128 GEMM + LN + ReLU (warp per node) -----------
__global__ void __launch_bounds__(256) k_gemm0_ln(const float* __restrict__ AF,
                                                  const float* __restrict__ W,
                                                  const float* __restrict__ b,
                                                  const float* __restrict__ gam,
                                                  const float* __restrict__ bet,
                                                  float* __restrict__ Y, int n) {
    __shared__ float sW[128 * 11];
    __shared__ float sb[128], sg[128], sbe[128];
    int tid = threadIdx.x;
    for (int i = tid; i < 128 * 11; i += 256) sW[i] = W[i];
    if (tid < 128) { sb[tid] = b[tid]; sg[tid] = gam[tid]; sbe[tid] = bet[tid]; }
    __syncthreads();
    int warp = tid >> 5, lane = tid & 31;
    int node = blockIdx.x * 8 + warp;
    if (node >= n) return;
    int deg = g_rowstart[node + 1] - g_rowstart[node];
    float f[11];
#pragma unroll
    for (int k = 0; k < 11; k++) f[k] = AF[node * 11 + k];
    int c0 = lane * 4;
    float a0 = sb[c0], a1 = sb[c0 + 1], a2 = sb[c0 + 2], a3 = sb[c0 + 3];
#pragma unroll
    for (int k = 0; k < 11; k++) {
        a0 += f[k] * sW[(c0 + 0) * 11 + k];
        a1 += f[k] * sW[(c0 + 1) * 11 + k];
        a2 += f[k] * sW[(c0 + 2) * 11 + k];
        a3 += f[k] * sW[(c0 + 3) * 11 + k];
    }
    if (deg == 0) { a0 = a1 = a2 = a3 = 0.f; }
    float mean = warp_sum(a0 + a1 + a2 + a3) * (1.0f / 128.0f);
    float d0 = a0 - mean, d1 = a1 - mean, d2 = a2 - mean, d3 = a3 - mean;
    float var = warp_sum(d0 * d0 + d1 * d1 + d2 * d2 + d3 * d3) * (1.0f / 128.0f);
    float rstd = rsqrtf(var + LN_EPS);
    float4 r;
    r.x = fmaxf(d0 * rstd * sg[c0 + 0] + sbe[c0 + 0], 0.f);
    r.y = fmaxf(d1 * rstd * sg[c0 + 1] + sbe[c0 + 1], 0.f);
    r.z = fmaxf(d2 * rstd * sg[c0 + 2] + sbe[c0 + 2], 0.f);
    r.w = fmaxf(d3 * rstd * sg[c0 + 3] + sbe[c0 + 3], 0.f);
    *(float4*)&Y[node * 128 + c0] = r;
}

// ---------------- tiled GEMM with packed f32x2 FMA -------------------------
// Y[n][NT] = X[n][128] * W[NT][128]^T + b.  128-row x NT-col tile, 256 thr,
// thread tile 8 rows x (NT/16) cols. X duplicated in smem so (a,a) packed
// operand is a single LDS.64; W col-pairs are half an LDS.128.
template <int NT>
__global__ void __launch_bounds__(256) k_gemm2(const float* __restrict__ X,
                                               const float* __restrict__ W,
                                               const float* __restrict__ bias,
                                               float* __restrict__ Y, int n) {
    const int NG = NT / 64;              // float4 col-groups per thread
    const int KC = 16;                   // k-chunk
    __shared__ float s_xd[128][2 * KC + 4];   // duplicated: [row][2k],[2k+1] = x
    __shared__ float s_w[KC][NT + 4];         // [k][col]
    int tid = threadIdx.x;
    int tx = tid & 15, ty = tid >> 4;
    int mBase = blockIdx.x * 128;
    unsigned long long acc[8][NG * 2];   // each ull = 2 adjacent cols
#pragma unroll
    for (int i = 0; i < 8; i++)
#pragma unroll
        for (int j = 0; j < NG * 2; j++) acc[i][j] = 0ull;

    for (int kc = 0; kc < 128; kc += KC) {
        // X tile: 128 rows x KC k = 512 float4 over 256 threads (2 iters)
#pragma unroll
        for (int it = 0; it < 2; it++) {
            int idx = tid + it * 256;
            int r = idx >> 2, q = idx & 3;          // q: which float4 of KC
            int gm = mBase + r;
            float4 v = make_float4(0.f, 0.f, 0.f, 0.f);
            if (gm < n) v = *(const float4*)&X[gm * 128 + kc + q * 4];
            *(float4*)&s_xd[r][8 * q]     = make_float4(v.x, v.x, v.y, v.y);
            *(float4*)&s_xd[r][8 * q + 4] = make_float4(v.z, v.z, v.w, v.w);
        }
        // W tile transposed: NT cols x KC k
#pragma unroll
        for (int it = 0; it < NT / 64; it++) {
            int idx = tid + it * 256;
            int c = idx >> 2, q = idx & 3;
            float4 w = *(const float4*)&W[c * 128 + kc + q * 4];
            s_w[q * 4 + 0][c] = w.x;
            s_w[q * 4 + 1][c] = w.y;
            s_w[q * 4 + 2][c] = w.z;
            s_w[q * 4 + 3][c] = w.w;
        }
        __syncthreads();
#pragma unroll
        for (int k = 0; k < KC; k++) {
            unsigned long long a2[8];
#pragma unroll
            for (int i = 0; i < 8; i++)
                a2[i] = *(const unsigned long long*)&s_xd[ty * 8 + i][2 * k];
#pragma unroll
            for (int g = 0; g < NG; g++) {
                u64x2 wv = *(const u64x2*)&s_w[k][g * 64 + tx * 4];
#pragma unroll
                for (int i = 0; i < 8; i++) {
                    ffma2(acc[i][g * 2 + 0], a2[i], wv.lo);
                    ffma2(acc[i][g * 2 + 1], a2[i], wv.hi);
                }
            }
        }
        __syncthreads();
    }
#pragma unroll
    for (int i = 0; i < 8; i++) {
        int m = mBase + ty * 8 + i;
        if (m < n) {
#pragma unroll
            for (int g = 0; g < NG; g++) {
                int c0 = g * 64 + tx * 4;
                float4 r;
                float lo, hi;
                unpack2(lo, hi, acc[i][g * 2 + 0]);
                r.x = lo + bias[c0 + 0];
                r.y = hi + bias[c0 + 1];
                unpack2(lo, hi, acc[i][g * 2 + 1]);
                r.z = lo + bias[c0 + 2];
                r.w = hi + bias[c0 + 3];
                *(float4*)&Y[m * NT + c0] = r;
            }
        }
    }
}

// ---------------- fused aggregate + degree-norm + LayerNorm (+ReLU) --------
template <int HD, bool RELU>
__global__ void k_agg_ln(const float* __restrict__ XT, const float* __restrict__ gam,
                         const float* __restrict__ bet, float* __restrict__ Y, int n) {
    int gw = (blockIdx.x * blockDim.x + threadIdx.x) >> 5;
    int lane = threadIdx.x & 31;
    if (gw >= n) return;
    int rs = g_rowstart[gw], re = g_rowstart[gw + 1];
    const int V = HD / 32;
    float acc[V];
#pragma unroll
    for (int i = 0; i < V; i++) acc[i] = 0.f;

    int e = rs;
    if constexpr (V == 4) {
        for (; e + 1 < re; e += 2) {
            int s0 = g_csr_src[e], s1 = g_csr_src[e + 1];
            float4 v0 = *(const float4*)&XT[s0 * HD + lane * 4];
            float4 v1 = *(const float4*)&XT[s1 * HD + lane * 4];
            acc[0] += v0.x + v1.x;
            acc[1] += v0.y + v1.y;
            acc[2] += v0.z + v1.z;
            acc[3] += v0.w + v1.w;
        }
        if (e < re) {
            int s0 = g_csr_src[e];
            float4 v0 = *(const float4*)&XT[s0 * HD + lane * 4];
            acc[0] += v0.x; acc[1] += v0.y; acc[2] += v0.z; acc[3] += v0.w;
        }
    } else {
        for (; e + 1 < re; e += 2) {
            int s0 = g_csr_src[e], s1 = g_csr_src[e + 1];
            float2 v0 = *(const float2*)&XT[s0 * HD + lane * 2];
            float2 v1 = *(const float2*)&XT[s1 * HD + lane * 2];
            acc[0] += v0.x + v1.x;
            acc[1] += v0.y + v1.y;
        }
        if (e < re) {
            int s0 = g_csr_src[e];
            float2 v0 = *(const float2*)&XT[s0 * HD + lane * 2];
            acc[0] += v0.x; acc[1] += v0.y;
        }
    }

    int deg = re - rs;
    float inv = 1.0f / (float)(deg > 0 ? deg : 1);
    float v[V];
    float psum = 0.f;
#pragma unroll
    for (int i = 0; i < V; i++) { v[i] = acc[i] * inv; psum += v[i]; }
    float mean = warp_sum(psum) * (1.0f / (float)HD);
    float d[V];
    float ps2 = 0.f;
#pragma unroll
    for (int i = 0; i < V; i++) { d[i] = v[i] - mean; ps2 += d[i] * d[i]; }
    float var = warp_sum(ps2) * (1.0f / (float)HD);
    float rstd = rsqrtf(var + LN_EPS);

    if constexpr (V == 4) {
        float4 G = *(const float4*)&gam[lane * 4];
        float4 B = *(const float4*)&bet[lane * 4];
        float4 r;
        r.x = d[0] * rstd * G.x + B.x;
        r.y = d[1] * rstd * G.y + B.y;
        r.z = d[2] * rstd * G.z + B.z;
        r.w = d[3] * rstd * G.w + B.w;
        if (RELU) {
            r.x = fmaxf(r.x, 0.f); r.y = fmaxf(r.y, 0.f);
            r.z = fmaxf(r.z, 0.f); r.w = fmaxf(r.w, 0.f);
        }
        *(float4*)&Y[gw * HD + lane * 4] = r;
    } else {
        float2 G = *(const float2*)&gam[lane * 2];
        float2 B = *(const float2*)&bet[lane * 2];
        float2 r;
        r.x = d[0] * rstd * G.x + B.x;
        r.y = d[1] * rstd * G.y + B.y;
        if (RELU) { r.x = fmaxf(r.x, 0.f); r.y = fmaxf(r.y, 0.f); }
        *(float2*)&Y[gw * HD + lane * 2] = r;
    }
}

// ---------------- launcher -------------------------------------------------
extern "C" void kernel_launch(void* const* d_in, const int* in_sizes, int n_in,
                              void* d_out, int out_size) {
    const float* nf  = (const float*)d_in[0];
    const int*   ei  = (const int*)d_in[1];
    const float* W0  = (const float*)d_in[2];
    const float* b0  = (const float*)d_in[3];
    const float* W1  = (const float*)d_in[4];
    const float* b1  = (const float*)d_in[5];
    const float* W2  = (const float*)d_in[6];
    const float* b2  = (const float*)d_in[7];
    const float* g0  = (const float*)d_in[8];
    const float* be0 = (const float*)d_in[9];
    const float* g1  = (const float*)d_in[10];
    const float* be1 = (const float*)d_in[11];
    const float* g2  = (const float*)d_in[12];
    const float* be2 = (const float*)d_in[13];

    int n = in_sizes[0] / 11;
    int e = in_sizes[1] / 2;
    const int* src = ei;
    const int* tgt = ei + e;

    float *bufA, *bufB;
    cudaGetSymbolAddress((void**)&bufA, g_buf_a);
    cudaGetSymbolAddress((void**)&bufB, g_buf_b);

    // CSR build (pull-style aggregation, no float atomics)
    k_zero_deg<<<(n + 255) / 256, 256>>>(n);
    k_count<<<(e + 255) / 256, 256>>>(tgt, e);
    k_scan<<<1, 1024>>>(n);
    k_fill<<<(e + 255) / 256, 256>>>(src, tgt, e);

    // layer 0: aggregate raw 11-wide features, then fused GEMM0+LN+ReLU
    k_agg_feat<<<(n + 15) / 16, 256>>>(nf, bufA, n);
    k_gemm0_ln<<<(n + 7) / 8, 256>>>(bufA, W0, b0, g0, be0, bufB, n);

    // layer 1: 128 -> 128
    k_gemm2<128><<<(n + 127) / 128, 256>>>(bufB, W1, b1, bufA, n);
    k_agg_ln<128, true><<<(n + 7) / 8, 256>>>(bufA, g1, be1, bufB, n);

    // layer 2: 128 -> 64
    k_gemm2<64><<<(n + 127) / 128, 256>>>(bufB, W2, b2, bufA, n);
    k_agg_ln<64, false><<<(n + 7) / 8, 256>>>(bufA, g2, be2, (float*)d_out, n);
}

// round 5
// speedup vs baseline: 1.4983x; 1.4277x over previous
#include <cuda_runtime.h>
#include <cuda_fp16.h>

#define NMAX 100000
#define EMAX 1600000
#define LN_EPS 1e-5f

// ---------------- scratch (device globals: no allocation allowed) ----------
__device__ int   g_deg[NMAX];
__device__ int   g_rowstart[NMAX + 1];
__device__ int   g_cursor[NMAX];
__device__ int   g_csr_src[EMAX];
__device__ int   g_bsum[256];
__device__ int   g_boff[256];
__device__ float g_buf_a[(size_t)NMAX * 128];
__device__ float g_buf_b[(size_t)NMAX * 128];
__device__ __half2 g_hbuf[(size_t)NMAX * 64];   // fp16 copy of GEMM outputs (gather operand)

// ---------------- packed fp32x2 FMA (sm_103a) ------------------------------
__device__ __forceinline__ void ffma2(unsigned long long& d, unsigned long long a,
                                      unsigned long long b) {
    asm("fma.rn.f32x2 %0, %1, %2, %0;" : "+l"(d) : "l"(a), "l"(b));
}
__device__ __forceinline__ void unpack2(float& lo, float& hi, unsigned long long v) {
    asm("mov.b64 {%0,%1}, %2;" : "=f"(lo), "=f"(hi) : "l"(v));
}
struct __align__(16) u64x2 { unsigned long long lo, hi; };
struct __align__(8) h2x2 { __half2 a, b; };

// ---------------- CSR build ------------------------------------------------
__global__ void k_zero_deg(int n) {
    int i = blockIdx.x * blockDim.x + threadIdx.x;
    if (i < n) g_deg[i] = 0;
}

__global__ void k_count(const int* __restrict__ tgt, int e) {
    int i = blockIdx.x * blockDim.x + threadIdx.x;
    if (i < e) atomicAdd(&g_deg[tgt[i]], 1);
}

// phase 1: per-block sum of 1024 degrees (coalesced)
__global__ void k_block_reduce(int n) {
    __shared__ int s[1024];
    int tid = threadIdx.x;
    int i = blockIdx.x * 1024 + tid;
    s[tid] = (i < n) ? g_deg[i] : 0;
    __syncthreads();
#pragma unroll
    for (int off = 512; off > 0; off >>= 1) {
        if (tid < off) s[tid] += s[tid + off];
        __syncthreads();
    }
    if (tid == 0) g_bsum[blockIdx.x] = s[0];
}

// phase 2: exclusive scan of the (<=256) block sums, one block
__global__ void k_scan_bsums(int nb) {
    __shared__ int s[256];
    int t = threadIdx.x;
    int v = (t < nb) ? g_bsum[t] : 0;
    s[t] = v;
    __syncthreads();
#pragma unroll
    for (int off = 1; off < 256; off <<= 1) {
        int u = (t >= off) ? s[t - off] : 0;
        __syncthreads();
        s[t] += u;
        __syncthreads();
    }
    if (t < nb) g_boff[t] = s[t] - v;   // exclusive
}

// phase 3: per-block exclusive scan + global offset (coalesced)
__global__ void k_scan_final(int n) {
    __shared__ int s[1024];
    int tid = threadIdx.x;
    int i = blockIdx.x * 1024 + tid;
    int v = (i < n) ? g_deg[i] : 0;
    s[tid] = v;
    __syncthreads();
#pragma unroll
    for (int off = 1; off < 1024; off <<= 1) {
        int u = (tid >= off) ? s[tid - off] : 0;
        __syncthreads();
        s[tid] += u;
        __syncthreads();
    }
    int excl = s[tid] - v + g_boff[blockIdx.x];
    if (i < n) {
        g_rowstart[i] = excl;
        g_cursor[i]   = excl;
        if (i == n - 1) g_rowstart[n] = excl + v;
    }
}

__global__ void k_fill(const int* __restrict__ src, const int* __restrict__ tgt, int e) {
    int i = blockIdx.x * blockDim.x + threadIdx.x;
    if (i < e) {
        int t = tgt[i];
        int pos = atomicAdd(&g_cursor[t], 1);
        g_csr_src[pos] = src[i];
    }
}

// ---------------- layer-0: aggregate RAW 11-wide features ------------------
__global__ void k_agg_feat(const float* __restrict__ X, float* __restrict__ out, int n) {
    int g = threadIdx.x >> 4, f = threadIdx.x & 15;
    int node = blockIdx.x * 16 + g;
    if (node >= n) return;
    int rs = g_rowstart[node], re = g_rowstart[node + 1];
    float acc = 0.f;
    for (int base = rs; base < re; base += 16) {
        int idx = base + f;
        int s = (idx < re) ? g_csr_src[idx] : 0;
#pragma unroll
        for (int j = 0; j < 16; j++) {
            int sj = __shfl_sync(0xffffffffu, s, j, 16);
            if (base + j < re && f < 11) acc += X[sj * 11 + f];
        }
    }
    float inv = 1.0f / (float)max(re - rs, 1);
    if (f < 11) out[node * 11 + f] = acc * inv;
}

__device__ __forceinline__ float warp_sum(float v) {
#pragma unroll
    for (int o = 16; o; o >>= 1) v += __shfl_xor_sync(0xffffffffu, v, o);
    return v;
}

// ---------------- fused 11->128 GEMM + LN + ReLU (warp per node) -----------
__global__ void __launch_bounds__(256) k_gemm0_ln(const float* __restrict__ AF,
                                                  const float* __restrict__ W,
                                                  const float* __restrict__ b,
                                                  const float* __restrict__ gam,
                                                  const float* __restrict__ bet,
                                                  float* __restrict__ Y, int n) {
    __shared__ float sW[128 * 11];
    __shared__ float sb[128], sg[128], sbe[128];
    int tid = threadIdx.x;
    for (int i = tid; i < 128 * 11; i += 256) sW[i] = W[i];
    if (tid < 128) { sb[tid] = b[tid]; sg[tid] = gam[tid]; sbe[tid] = bet[tid]; }
    __syncthreads();
    int warp = tid >> 5, lane = tid & 31;
    int node = blockIdx.x * 8 + warp;
    if (node >= n) return;
    int deg = g_rowstart[node + 1] - g_rowstart[node];
    float f[11];
#pragma unroll
    for (int k = 0; k < 11; k++) f[k] = AF[node * 11 + k];
    int c0 = lane * 4;
    float a0 = sb[c0], a1 = sb[c0 + 1], a2 = sb[c0 + 2], a3 = sb[c0 + 3];
#pragma unroll
    for (int k = 0; k < 11; k++) {
        a0 += f[k] * sW[(c0 + 0) * 11 + k];
        a1 += f[k] * sW[(c0 + 1) * 11 + k];
        a2 += f[k] * sW[(c0 + 2) * 11 + k];
        a3 += f[k] * sW[(c0 + 3) * 11 + k];
    }
    if (deg == 0) { a0 = a1 = a2 = a3 = 0.f; }
    float mean = warp_sum(a0 + a1 + a2 + a3) * (1.0f / 128.0f);
    float d0 = a0 - mean, d1 = a1 - mean, d2 = a2 - mean, d3 = a3 - mean;
    float var = warp_sum(d0 * d0 + d1 * d1 + d2 * d2 + d3 * d3) * (1.0f / 128.0f);
    float rstd = rsqrtf(var + LN_EPS);
    float4 r;
    r.x = fmaxf(d0 * rstd * sg[c0 + 0] + sbe[c0 + 0], 0.f);
    r.y = fmaxf(d1 * rstd * sg[c0 + 1] + sbe[c0 + 1], 0.f);
    r.z = fmaxf(d2 * rstd * sg[c0 + 2] + sbe[c0 + 2], 0.f);
    r.w = fmaxf(d3 * rstd * sg[c0 + 3] + sbe[c0 + 3], 0.f);
    *(float4*)&Y[node * 128 + c0] = r;
}

// ---------------- tiled GEMM with packed f32x2 FMA, half2 output -----------
// Yh[n][NT/2] = half( X[n][128] * W[NT][128]^T + b )
template <int NT>
__global__ void __launch_bounds__(256) k_gemm2(const float* __restrict__ X,
                                               const float* __restrict__ W,
                                               const float* __restrict__ bias,
                                               __half2* __restrict__ Yh, int n) {
    const int NG = NT / 64;
    const int KC = 16;
    __shared__ float s_xd[128][2 * KC + 4];
    __shared__ float s_w[KC][NT + 4];
    int tid = threadIdx.x;
    int tx = tid & 15, ty = tid >> 4;
    int mBase = blockIdx.x * 128;
    unsigned long long acc[8][NG * 2];
#pragma unroll
    for (int i = 0; i < 8; i++)
#pragma unroll
        for (int j = 0; j < NG * 2; j++) acc[i][j] = 0ull;

    for (int kc = 0; kc < 128; kc += KC) {
#pragma unroll
        for (int it = 0; it < 2; it++) {
            int idx = tid + it * 256;
            int r = idx >> 2, q = idx & 3;
            int gm = mBase + r;
            float4 v = make_float4(0.f, 0.f, 0.f, 0.f);
            if (gm < n) v = *(const float4*)&X[gm * 128 + kc + q * 4];
            *(float4*)&s_xd[r][8 * q]     = make_float4(v.x, v.x, v.y, v.y);
            *(float4*)&s_xd[r][8 * q + 4] = make_float4(v.z, v.z, v.w, v.w);
        }
#pragma unroll
        for (int it = 0; it < NT / 64; it++) {
            int idx = tid + it * 256;
            int c = idx >> 2, q = idx & 3;
            float4 w = *(const float4*)&W[c * 128 + kc + q * 4];
            s_w[q * 4 + 0][c] = w.x;
            s_w[q * 4 + 1][c] = w.y;
            s_w[q * 4 + 2][c] = w.z;
            s_w[q * 4 + 3][c] = w.w;
        }
        __syncthreads();
#pragma unroll
        for (int k = 0; k < KC; k++) {
            unsigned long long a2[8];
#pragma unroll
            for (int i = 0; i < 8; i++)
                a2[i] = *(const unsigned long long*)&s_xd[ty * 8 + i][2 * k];
#pragma unroll
            for (int g = 0; g < NG; g++) {
                u64x2 wv = *(const u64x2*)&s_w[k][g * 64 + tx * 4];
#pragma unroll
                for (int i = 0; i < 8; i++) {
                    ffma2(acc[i][g * 2 + 0], a2[i], wv.lo);
                    ffma2(acc[i][g * 2 + 1], a2[i], wv.hi);
                }
            }
        }
        __syncthreads();
    }
#pragma unroll
    for (int i = 0; i < 8; i++) {
        int m = mBase + ty * 8 + i;
        if (m < n) {
#pragma unroll
            for (int g = 0; g < NG; g++) {
                int c0 = g * 64 + tx * 4;
                float lo, hi;
                float2 p0, p1;
                unpack2(lo, hi, acc[i][g * 2 + 0]);
                p0.x = lo + bias[c0 + 0];
                p0.y = hi + bias[c0 + 1];
                unpack2(lo, hi, acc[i][g * 2 + 1]);
                p1.x = lo + bias[c0 + 2];
                p1.y = hi + bias[c0 + 3];
                h2x2 hh;
                hh.a = __float22half2_rn(p0);
                hh.b = __float22half2_rn(p1);
                *(h2x2*)&Yh[(size_t)m * (NT / 2) + c0 / 2] = hh;
            }
        }
    }
}

// ---------------- fused aggregate (fp16 in) + deg-norm + LN (+ReLU) --------
__device__ __forceinline__ void acc_row128(float* acc, const __half2* __restrict__ X,
                                           int s, int lane) {
    uint2 u = *(const uint2*)&X[(size_t)s * 64 + lane * 2];
    __half2 h0 = *(__half2*)&u.x, h1 = *(__half2*)&u.y;
    float2 f0 = __half22float2(h0), f1 = __half22float2(h1);
    acc[0] += f0.x; acc[1] += f0.y; acc[2] += f1.x; acc[3] += f1.y;
}

template <int HD, bool RELU>
__global__ void k_agg_ln(const __half2* __restrict__ XT, const float* __restrict__ gam,
                         const float* __restrict__ bet, float* __restrict__ Y, int n) {
    int gw = (blockIdx.x * blockDim.x + threadIdx.x) >> 5;
    int lane = threadIdx.x & 31;
    if (gw >= n) return;
    int rs = g_rowstart[gw], re = g_rowstart[gw + 1];
    const int V = HD / 32;
    float acc[V];
#pragma unroll
    for (int i = 0; i < V; i++) acc[i] = 0.f;

    int e = rs;
    if constexpr (V == 4) {
        for (; e + 3 < re; e += 4) {
            int s0 = g_csr_src[e + 0], s1 = g_csr_src[e + 1];
            int s2 = g_csr_src[e + 2], s3 = g_csr_src[e + 3];
            acc_row128(acc, XT, s0, lane);
            acc_row128(acc, XT, s1, lane);
            acc_row128(acc, XT, s2, lane);
            acc_row128(acc, XT, s3, lane);
        }
        for (; e < re; e++) acc_row128(acc, XT, g_csr_src[e], lane);
    } else {
        for (; e + 3 < re; e += 4) {
            int s0 = g_csr_src[e + 0], s1 = g_csr_src[e + 1];
            int s2 = g_csr_src[e + 2], s3 = g_csr_src[e + 3];
            float2 f0 = __half22float2(XT[(size_t)s0 * 32 + lane]);
            float2 f1 = __half22float2(XT[(size_t)s1 * 32 + lane]);
            float2 f2 = __half22float2(XT[(size_t)s2 * 32 + lane]);
            float2 f3 = __half22float2(XT[(size_t)s3 * 32 + lane]);
            acc[0] += (f0.x + f1.x) + (f2.x + f3.x);
            acc[1] += (f0.y + f1.y) + (f2.y + f3.y);
        }
        for (; e < re; e++) {
            float2 f0 = __half22float2(XT[(size_t)g_csr_src[e] * 32 + lane]);
            acc[0] += f0.x; acc[1] += f0.y;
        }
    }

    int deg = re - rs;
    float inv = 1.0f / (float)(deg > 0 ? deg : 1);
    float v[V];
    float psum = 0.f;
#pragma unroll
    for (int i = 0; i < V; i++) { v[i] = acc[i] * inv; psum += v[i]; }
    float mean = warp_sum(psum) * (1.0f / (float)HD);
    float d[V];
    float ps2 = 0.f;
#pragma unroll
    for (int i = 0; i < V; i++) { d[i] = v[i] - mean; ps2 += d[i] * d[i]; }
    float var = warp_sum(ps2) * (1.0f / (float)HD);
    float rstd = rsqrtf(var + LN_EPS);

    if constexpr (V == 4) {
        float4 G = *(const float4*)&gam[lane * 4];
        float4 B = *(const float4*)&bet[lane * 4];
        float4 r;
        r.x = d[0] * rstd * G.x + B.x;
        r.y = d[1] * rstd * G.y + B.y;
        r.z = d[2] * rstd * G.z + B.z;
        r.w = d[3] * rstd * G.w + B.w;
        if (RELU) {
            r.x = fmaxf(r.x, 0.f); r.y = fmaxf(r.y, 0.f);
            r.z = fmaxf(r.z, 0.f); r.w = fmaxf(r.w, 0.f);
        }
        *(float4*)&Y[(size_t)gw * HD + lane * 4] = r;
    } else {
        float2 G = *(const float2*)&gam[lane * 2];
        float2 B = *(const float2*)&bet[lane * 2];
        float2 r;
        r.x = d[0] * rstd * G.x + B.x;
        r.y = d[1] * rstd * G.y + B.y;
        if (RELU) { r.x = fmaxf(r.x, 0.f); r.y = fmaxf(r.y, 0.f); }
        *(float2*)&Y[(size_t)gw * HD + lane * 2] = r;
    }
}

// ---------------- launcher -------------------------------------------------
extern "C" void kernel_launch(void* const* d_in, const int* in_sizes, int n_in,
                              void* d_out, int out_size) {
    const float* nf  = (const float*)d_in[0];
    const int*   ei  = (const int*)d_in[1];
    const float* W0  = (const float*)d_in[2];
    const float* b0  = (const float*)d_in[3];
    const float* W1  = (const float*)d_in[4];
    const float* b1  = (const float*)d_in[5];
    const float* W2  = (const float*)d_in[6];
    const float* b2  = (const float*)d_in[7];
    const float* g0  = (const float*)d_in[8];
    const float* be0 = (const float*)d_in[9];
    const float* g1  = (const float*)d_in[10];
    const float* be1 = (const float*)d_in[11];
    const float* g2  = (const float*)d_in[12];
    const float* be2 = (const float*)d_in[13];

    int n = in_sizes[0] / 11;
    int e = in_sizes[1] / 2;
    const int* src = ei;
    const int* tgt = ei + e;
    int nb = (n + 1023) / 1024;

    float *bufA, *bufB;
    __half2* hbuf;
    cudaGetSymbolAddress((void**)&bufA, g_buf_a);
    cudaGetSymbolAddress((void**)&bufB, g_buf_b);
    cudaGetSymbolAddress((void**)&hbuf, g_hbuf);

    // CSR build: histogram + coalesced 3-phase scan + scatter fill
    k_zero_deg<<<(n + 255) / 256, 256>>>(n);
    k_count<<<(e + 255) / 256, 256>>>(tgt, e);
    k_block_reduce<<<nb, 1024>>>(n);
    k_scan_bsums<<<1, 256>>>(nb);
    k_scan_final<<<nb, 1024>>>(n);
    k_fill<<<(e + 255) / 256, 256>>>(src, tgt, e);

    // layer 0: aggregate raw 11-wide features, then fused GEMM0+LN+ReLU
    k_agg_feat<<<(n + 15) / 16, 256>>>(nf, bufA, n);
    k_gemm0_ln<<<(n + 7) / 8, 256>>>(bufA, W0, b0, g0, be0, bufB, n);

    // layer 1: 128 -> 128 (fp16 gather operand)
    k_gemm2<128><<<(n + 127) / 128, 256>>>(bufB, W1, b1, hbuf, n);
    k_agg_ln<128, true><<<(n + 7) / 8, 256>>>(hbuf, g1, be1, bufA, n);

    // layer 2: 128 -> 64 (fp16 gather operand)
    k_gemm2<64><<<(n + 127) / 128, 256>>>(bufA, W2, b2, hbuf, n);
    k_agg_ln<64, false><<<(n + 7) / 8, 256>>>(hbuf, g2, be2, (float*)d_out, n);
}

// round 6
// speedup vs baseline: 2.3705x; 1.5821x over previous
#include <cuda_runtime.h>
#include <cuda_fp16.h>

#define NMAX 100000
#define EMAX 1600000
#define LN_EPS 1e-5f

// ---------------- scratch (device globals: no allocation allowed) ----------
__device__ int   g_deg[NMAX];
__device__ int   g_rowstart[NMAX + 1];
__device__ int   g_cursor[NMAX];
__device__ int   g_csr_src[EMAX];
__device__ int   g_bsum[128];
__device__ float g_buf_a[(size_t)NMAX * 16];          // agg_feat output (11-wide)
__device__ __half2 g_hx[(size_t)NMAX * 64];           // GEMM input activations
__device__ __half2 g_hy[(size_t)NMAX * 64];           // GEMM output / gather operand
__device__ __half  g_hW1[128 * 128];
__device__ __half  g_hW2[64 * 128];

// ---------------- helpers --------------------------------------------------
__device__ __forceinline__ unsigned smem_u32(const void* p) {
    unsigned a;
    asm("{ .reg .u64 t; cvta.to.shared.u64 t, %1; cvt.u32.u64 %0, t; }"
        : "=r"(a) : "l"(p));
    return a;
}
__device__ __forceinline__ void ldmx4(unsigned* r, unsigned addr) {
    asm volatile("ldmatrix.sync.aligned.m8n8.x4.shared.b16 {%0,%1,%2,%3}, [%4];"
                 : "=r"(r[0]), "=r"(r[1]), "=r"(r[2]), "=r"(r[3]) : "r"(addr));
}
__device__ __forceinline__ void mma16816(float* c, const unsigned* a, unsigned b0,
                                         unsigned b1) {
    asm volatile(
        "mma.sync.aligned.m16n8k16.row.col.f32.f16.f16.f32 "
        "{%0,%1,%2,%3},{%4,%5,%6,%7},{%8,%9},{%0,%1,%2,%3};"
        : "+f"(c[0]), "+f"(c[1]), "+f"(c[2]), "+f"(c[3])
        : "r"(a[0]), "r"(a[1]), "r"(a[2]), "r"(a[3]), "r"(b0), "r"(b1));
}
__device__ __forceinline__ float warp_sum(float v) {
#pragma unroll
    for (int o = 16; o; o >>= 1) v += __shfl_xor_sync(0xffffffffu, v, o);
    return v;
}

// ---------------- CSR build ------------------------------------------------
__global__ void k_count(const int* __restrict__ tgt, int e) {
    int i = blockIdx.x * blockDim.x + threadIdx.x;
    if (i < e) atomicAdd(&g_deg[tgt[i]], 1);
}

__global__ void k_block_reduce(int n) {
    __shared__ int s[1024];
    int tid = threadIdx.x;
    int i = blockIdx.x * 1024 + tid;
    s[tid] = (i < n) ? g_deg[i] : 0;
    __syncthreads();
#pragma unroll
    for (int off = 512; off > 0; off >>= 1) {
        if (tid < off) s[tid] += s[tid + off];
        __syncthreads();
    }
    if (tid == 0) g_bsum[blockIdx.x] = s[0];
}

// fused: every block scans the (<=128) block sums itself, then scans its tile
__global__ void k_scan_final(int n, int nb) {
    __shared__ int sb[128];
    __shared__ int s[1024];
    int tid = threadIdx.x;
    if (tid < 128) sb[tid] = (tid < nb) ? g_bsum[tid] : 0;
    __syncthreads();
#pragma unroll
    for (int off = 1; off < 128; off <<= 1) {
        int u = (tid < 128 && tid >= off) ? sb[tid - off] : 0;
        __syncthreads();
        if (tid < 128) sb[tid] += u;
        __syncthreads();
    }
    int boff = (blockIdx.x > 0) ? sb[blockIdx.x - 1] : 0;

    int i = blockIdx.x * 1024 + tid;
    int v = (i < n) ? g_deg[i] : 0;
    s[tid] = v;
    __syncthreads();
#pragma unroll
    for (int off = 1; off < 1024; off <<= 1) {
        int u = (tid >= off) ? s[tid - off] : 0;
        __syncthreads();
        s[tid] += u;
        __syncthreads();
    }
    int excl = s[tid] - v + boff;
    if (i < n) {
        g_rowstart[i] = excl;
        g_cursor[i]   = excl;
        if (i == n - 1) g_rowstart[n] = excl + v;
    }
}

__global__ void k_fill(const int* __restrict__ src, const int* __restrict__ tgt, int e) {
    int i = blockIdx.x * blockDim.x + threadIdx.x;
    if (i < e) {
        int t = tgt[i];
        int pos = atomicAdd(&g_cursor[t], 1);
        g_csr_src[pos] = src[i];
    }
}

// ---------------- weight fp32 -> fp16 --------------------------------------
__global__ void k_cvtW(const float* __restrict__ W1, const float* __restrict__ W2) {
    int i = blockIdx.x * 256 + threadIdx.x;
    if (i < 128 * 128) g_hW1[i] = __float2half(W1[i]);
    if (i < 64 * 128)  g_hW2[i] = __float2half(W2[i]);
}

// ---------------- layer-0: aggregate RAW 11-wide features ------------------
__global__ void k_agg_feat(const float* __restrict__ X, float* __restrict__ out, int n) {
    int g = threadIdx.x >> 4, f = threadIdx.x & 15;
    int node = blockIdx.x * 16 + g;
    if (node >= n) return;
    int rs = g_rowstart[node], re = g_rowstart[node + 1];
    float acc = 0.f;
    for (int base = rs; base < re; base += 16) {
        int idx = base + f;
        int s = (idx < re) ? g_csr_src[idx] : 0;
#pragma unroll
        for (int j = 0; j < 16; j++) {
            int sj = __shfl_sync(0xffffffffu, s, j, 16);
            if (base + j < re && f < 11) acc += X[sj * 11 + f];
        }
    }
    float inv = 1.0f / (float)max(re - rs, 1);
    if (f < 11) out[node * 16 + f] = acc * inv;
}

// ---------------- fused 11->128 GEMM + LN + ReLU -> fp16 -------------------
__global__ void __launch_bounds__(256) k_gemm0_ln(const float* __restrict__ AF,
                                                  const float* __restrict__ W,
                                                  const float* __restrict__ b,
                                                  const float* __restrict__ gam,
                                                  const float* __restrict__ bet,
                                                  __half2* __restrict__ Yh, int n) {
    __shared__ float sW[128 * 11];
    __shared__ float sb[128], sg[128], sbe[128];
    int tid = threadIdx.x;
    for (int i = tid; i < 128 * 11; i += 256) sW[i] = W[i];
    if (tid < 128) { sb[tid] = b[tid]; sg[tid] = gam[tid]; sbe[tid] = bet[tid]; }
    __syncthreads();
    int warp = tid >> 5, lane = tid & 31;
    int node = blockIdx.x * 8 + warp;
    if (node >= n) return;
    int deg = g_rowstart[node + 1] - g_rowstart[node];
    float f[11];
#pragma unroll
    for (int k = 0; k < 11; k++) f[k] = AF[node * 16 + k];
    int c0 = lane * 4;
    float a0 = sb[c0], a1 = sb[c0 + 1], a2 = sb[c0 + 2], a3 = sb[c0 + 3];
#pragma unroll
    for (int k = 0; k < 11; k++) {
        a0 += f[k] * sW[(c0 + 0) * 11 + k];
        a1 += f[k] * sW[(c0 + 1) * 11 + k];
        a2 += f[k] * sW[(c0 + 2) * 11 + k];
        a3 += f[k] * sW[(c0 + 3) * 11 + k];
    }
    if (deg == 0) { a0 = a1 = a2 = a3 = 0.f; }
    float mean = warp_sum(a0 + a1 + a2 + a3) * (1.0f / 128.0f);
    float d0 = a0 - mean, d1 = a1 - mean, d2 = a2 - mean, d3 = a3 - mean;
    float var = warp_sum(d0 * d0 + d1 * d1 + d2 * d2 + d3 * d3) * (1.0f / 128.0f);
    float rstd = rsqrtf(var + LN_EPS);
    float rx = fmaxf(d0 * rstd * sg[c0 + 0] + sbe[c0 + 0], 0.f);
    float ry = fmaxf(d1 * rstd * sg[c0 + 1] + sbe[c0 + 1], 0.f);
    float rz = fmaxf(d2 * rstd * sg[c0 + 2] + sbe[c0 + 2], 0.f);
    float rw = fmaxf(d3 * rstd * sg[c0 + 3] + sbe[c0 + 3], 0.f);
    __half2 h0 = __floats2half2_rn(rx, ry);
    __half2 h1 = __floats2half2_rn(rz, rw);
    uint2 u;
    u.x = *(unsigned*)&h0;
    u.y = *(unsigned*)&h1;
    *(uint2*)&Yh[(size_t)node * 64 + lane * 2] = u;
}

// ---------------- tensor-core GEMM: Yh[n][NT] = half(Xh * Wh^T + b) --------
// 128-row x NT-col block tile, 8 warps (4x2), warp tile 32 x NT/2.
// smem: padded stride 72 halfs (144B) -> ldmatrix conflict-free.
template <int NT>
__global__ void __launch_bounds__(256, 2) k_mma(const __half* __restrict__ X,
                                                const __half* __restrict__ Wh,
                                                const float* __restrict__ bias,
                                                __half2* __restrict__ Yh, int n) {
    const int WN = NT / 2;
    __shared__ __half sx[128 * 72];
    __shared__ __half sw[NT * 72];
    int tid = threadIdx.x, lane = tid & 31, wid = tid >> 5;
    int wy = wid >> 1, wx = wid & 1;
    int mBase = blockIdx.x * 128;
    int r8 = lane & 7, sub = lane >> 3;
    unsigned sxb = smem_u32(sx), swb = smem_u32(sw);

    float c[2][WN / 8][4];
#pragma unroll
    for (int mi = 0; mi < 2; mi++)
#pragma unroll
        for (int nb = 0; nb < WN / 8; nb++)
#pragma unroll
            for (int q = 0; q < 4; q++) c[mi][nb][q] = 0.f;

    for (int kc = 0; kc < 128; kc += 64) {
#pragma unroll
        for (int it = 0; it < 4; it++) {
            int idx = tid + it * 256;
            int r = idx >> 3, c8 = idx & 7;
            int gm = mBase + r;
            uint4 v = make_uint4(0u, 0u, 0u, 0u);
            if (gm < n) v = ((const uint4*)X)[(size_t)gm * 16 + (kc >> 3) + c8];
            *(uint4*)&sx[r * 72 + c8 * 8] = v;
        }
#pragma unroll
        for (int it = 0; it < NT / 32; it++) {
            int idx = tid + it * 256;
            int r = idx >> 3, c8 = idx & 7;
            uint4 v = ((const uint4*)Wh)[r * 16 + (kc >> 3) + c8];
            *(uint4*)&sw[r * 72 + c8 * 8] = v;
        }
        __syncthreads();
#pragma unroll
        for (int ks = 0; ks < 4; ks++) {
            int k0 = ks * 16;
            unsigned a[2][4];
#pragma unroll
            for (int mi = 0; mi < 2; mi++) {
                int row = wy * 32 + mi * 16 + r8 + ((sub & 1) << 3);
                int kof = k0 + ((sub >> 1) << 3);
                ldmx4(a[mi], sxb + (row * 72 + kof) * 2);
            }
            unsigned bf[WN / 8][2];
#pragma unroll
            for (int nb = 0; nb < WN / 16; nb++) {
                int n0 = wx * WN + nb * 16;
                int row = n0 + r8 + ((sub >> 1) << 3);
                int kof = k0 + ((sub & 1) << 3);
                unsigned t4[4];
                ldmx4(t4, swb + (row * 72 + kof) * 2);
                bf[2 * nb][0] = t4[0];
                bf[2 * nb][1] = t4[1];
                bf[2 * nb + 1][0] = t4[2];
                bf[2 * nb + 1][1] = t4[3];
            }
#pragma unroll
            for (int mi = 0; mi < 2; mi++)
#pragma unroll
                for (int nb = 0; nb < WN / 8; nb++)
                    mma16816(c[mi][nb], a[mi], bf[nb][0], bf[nb][1]);
        }
        __syncthreads();
    }

    int g = lane >> 2, t = lane & 3;
#pragma unroll
    for (int mi = 0; mi < 2; mi++) {
        int row0 = mBase + wy * 32 + mi * 16 + g;
#pragma unroll
        for (int nb = 0; nb < WN / 8; nb++) {
            int col = wx * WN + nb * 8 + 2 * t;
            float2 bv = *(const float2*)&bias[col];
            if (row0 < n) {
                __half2 h = __floats2half2_rn(c[mi][nb][0] + bv.x, c[mi][nb][1] + bv.y);
                Yh[(size_t)row0 * (NT / 2) + (col >> 1)] = h;
            }
            int row1 = row0 + 8;
            if (row1 < n) {
                __half2 h = __floats2half2_rn(c[mi][nb][2] + bv.x, c[mi][nb][3] + bv.y);
                Yh[(size_t)row1 * (NT / 2) + (col >> 1)] = h;
            }
        }
    }
}

// ---------------- fused aggregate (fp16 in) + deg-norm + LN (+ReLU) --------
__device__ __forceinline__ void acc_row128(float* acc, const __half2* __restrict__ X,
                                           int s, int lane) {
    uint2 u = *(const uint2*)&X[(size_t)s * 64 + lane * 2];
    __half2 h0 = *(__half2*)&u.x, h1 = *(__half2*)&u.y;
    float2 f0 = __half22float2(h0), f1 = __half22float2(h1);
    acc[0] += f0.x; acc[1] += f0.y; acc[2] += f1.x; acc[3] += f1.y;
}

template <int HD, bool RELU, bool HOUT>
__global__ void k_agg_ln(const __half2* __restrict__ XT, const float* __restrict__ gam,
                         const float* __restrict__ bet, void* __restrict__ out, int n) {
    int gw = (blockIdx.x * blockDim.x + threadIdx.x) >> 5;
    int lane = threadIdx.x & 31;
    if (gw >= n) return;
    int rs = g_rowstart[gw], re = g_rowstart[gw + 1];
    const int V = HD / 32;
    float acc[V];
#pragma unroll
    for (int i = 0; i < V; i++) acc[i] = 0.f;

    int e = rs;
    if constexpr (V == 4) {
        for (; e + 3 < re; e += 4) {
            int s0 = g_csr_src[e + 0], s1 = g_csr_src[e + 1];
            int s2 = g_csr_src[e + 2], s3 = g_csr_src[e + 3];
            acc_row128(acc, XT, s0, lane);
            acc_row128(acc, XT, s1, lane);
            acc_row128(acc, XT, s2, lane);
            acc_row128(acc, XT, s3, lane);
        }
        for (; e < re; e++) acc_row128(acc, XT, g_csr_src[e], lane);
    } else {
        for (; e + 3 < re; e += 4) {
            int s0 = g_csr_src[e + 0], s1 = g_csr_src[e + 1];
            int s2 = g_csr_src[e + 2], s3 = g_csr_src[e + 3];
            float2 f0 = __half22float2(XT[(size_t)s0 * 32 + lane]);
            float2 f1 = __half22float2(XT[(size_t)s1 * 32 + lane]);
            float2 f2 = __half22float2(XT[(size_t)s2 * 32 + lane]);
            float2 f3 = __half22float2(XT[(size_t)s3 * 32 + lane]);
            acc[0] += (f0.x + f1.x) + (f2.x + f3.x);
            acc[1] += (f0.y + f1.y) + (f2.y + f3.y);
        }
        for (; e < re; e++) {
            float2 f0 = __half22float2(XT[(size_t)g_csr_src[e] * 32 + lane]);
            acc[0] += f0.x; acc[1] += f0.y;
        }
    }

    int deg = re - rs;
    float inv = 1.0f / (float)(deg > 0 ? deg : 1);
    float v[V];
    float psum = 0.f;
#pragma unroll
    for (int i = 0; i < V; i++) { v[i] = acc[i] * inv; psum += v[i]; }
    float mean = warp_sum(psum) * (1.0f / (float)HD);
    float d[V];
    float ps2 = 0.f;
#pragma unroll
    for (int i = 0; i < V; i++) { d[i] = v[i] - mean; ps2 += d[i] * d[i]; }
    float var = warp_sum(ps2) * (1.0f / (float)HD);
    float rstd = rsqrtf(var + LN_EPS);

    if constexpr (V == 4) {
        float4 G = *(const float4*)&gam[lane * 4];
        float4 B = *(const float4*)&bet[lane * 4];
        float rx = d[0] * rstd * G.x + B.x;
        float ry = d[1] * rstd * G.y + B.y;
        float rz = d[2] * rstd * G.z + B.z;
        float rw = d[3] * rstd * G.w + B.w;
        if (RELU) {
            rx = fmaxf(rx, 0.f); ry = fmaxf(ry, 0.f);
            rz = fmaxf(rz, 0.f); rw = fmaxf(rw, 0.f);
        }
        if constexpr (HOUT) {
            __half2 h0 = __floats2half2_rn(rx, ry);
            __half2 h1 = __floats2half2_rn(rz, rw);
            uint2 u;
            u.x = *(unsigned*)&h0;
            u.y = *(unsigned*)&h1;
            *(uint2*)&((__half2*)out)[(size_t)gw * 64 + lane * 2] = u;
        } else {
            float4 r = make_float4(rx, ry, rz, rw);
            *(float4*)&((float*)out)[(size_t)gw * HD + lane * 4] = r;
        }
    } else {
        float2 G = *(const float2*)&gam[lane * 2];
        float2 B = *(const float2*)&bet[lane * 2];
        float2 r;
        r.x = d[0] * rstd * G.x + B.x;
        r.y = d[1] * rstd * G.y + B.y;
        if (RELU) { r.x = fmaxf(r.x, 0.f); r.y = fmaxf(r.y, 0.f); }
        *(float2*)&((float*)out)[(size_t)gw * HD + lane * 2] = r;
    }
}

// ---------------- launcher -------------------------------------------------
extern "C" void kernel_launch(void* const* d_in, const int* in_sizes, int n_in,
                              void* d_out, int out_size) {
    const float* nf  = (const float*)d_in[0];
    const int*   ei  = (const int*)d_in[1];
    const float* W0  = (const float*)d_in[2];
    const float* b0  = (const float*)d_in[3];
    const float* W1  = (const float*)d_in[4];
    const float* b1  = (const float*)d_in[5];
    const float* W2  = (const float*)d_in[6];
    const float* b2  = (const float*)d_in[7];
    const float* g0  = (const float*)d_in[8];
    const float* be0 = (const float*)d_in[9];
    const float* g1  = (const float*)d_in[10];
    const float* be1 = (const float*)d_in[11];
    const float* g2  = (const float*)d_in[12];
    const float* be2 = (const float*)d_in[13];

    int n = in_sizes[0] / 11;
    int e = in_sizes[1] / 2;
    const int* src = ei;
    const int* tgt = ei + e;
    int nb = (n + 1023) / 1024;

    float* bufA;
    __half2 *hX, *hY;
    __half *hW1, *hW2;
    int* degp;
    cudaGetSymbolAddress((void**)&bufA, g_buf_a);
    cudaGetSymbolAddress((void**)&hX, g_hx);
    cudaGetSymbolAddress((void**)&hY, g_hy);
    cudaGetSymbolAddress((void**)&hW1, g_hW1);
    cudaGetSymbolAddress((void**)&hW2, g_hW2);
    cudaGetSymbolAddress((void**)&degp, g_deg);

    // CSR build
    cudaMemsetAsync(degp, 0, n * sizeof(int));
    k_count<<<(e + 255) / 256, 256>>>(tgt, e);
    k_block_reduce<<<nb, 1024>>>(n);
    k_scan_final<<<nb, 1024>>>(n, nb);
    k_fill<<<(e + 255) / 256, 256>>>(src, tgt, e);
    k_cvtW<<<64, 256>>>(W1, W2);

    // layer 0
    k_agg_feat<<<(n + 15) / 16, 256>>>(nf, bufA, n);
    k_gemm0_ln<<<(n + 7) / 8, 256>>>(bufA, W0, b0, g0, be0, hX, n);

    // layer 1: 128 -> 128 (tensor cores)
    k_mma<128><<<(n + 127) / 128, 256>>>((const __half*)hX, hW1, b1, hY, n);
    k_agg_ln<128, true, true><<<(n + 7) / 8, 256>>>(hY, g1, be1, hX, n);

    // layer 2: 128 -> 64 (tensor cores)
    k_mma<64><<<(n + 127) / 128, 256>>>((const __half*)hX, hW2, b2, hY, n);
    k_agg_ln<64, false, false><<<(n + 7) / 8, 256>>>(hY, g2, be2, d_out, n);
}

// round 7
// speedup vs baseline: 2.5911x; 1.0931x over previous
#include <cuda_runtime.h>
#include <cuda_fp16.h>

#define NMAX 100000
#define EMAX 1600000
#define CAP 96
#define LN_EPS 1e-5f

// ---------------- scratch (device globals: no allocation allowed) ----------
__device__ int   g_cursor[NMAX];
__device__ int   g_pad[(size_t)NMAX * CAP];           // padded adjacency (src ids)
__device__ float g_buf_a[(size_t)NMAX * 16];          // agg_feat output (11-wide)
__device__ __half2 g_hx[(size_t)NMAX * 64];           // GEMM input activations
__device__ __half2 g_hy[(size_t)NMAX * 64];           // GEMM output / gather operand
__device__ __half  g_hW1[128 * 128];
__device__ __half  g_hW2[64 * 128];

// ---------------- helpers --------------------------------------------------
__device__ __forceinline__ unsigned smem_u32(const void* p) {
    unsigned a;
    asm("{ .reg .u64 t; cvta.to.shared.u64 t, %1; cvt.u32.u64 %0, t; }"
        : "=r"(a) : "l"(p));
    return a;
}
__device__ __forceinline__ void ldmx4(unsigned* r, unsigned addr) {
    asm volatile("ldmatrix.sync.aligned.m8n8.x4.shared.b16 {%0,%1,%2,%3}, [%4];"
                 : "=r"(r[0]), "=r"(r[1]), "=r"(r[2]), "=r"(r[3]) : "r"(addr));
}
__device__ __forceinline__ void mma16816(float* c, const unsigned* a, unsigned b0,
                                         unsigned b1) {
    asm volatile(
        "mma.sync.aligned.m16n8k16.row.col.f32.f16.f16.f32 "
        "{%0,%1,%2,%3},{%4,%5,%6,%7},{%8,%9},{%0,%1,%2,%3};"
        : "+f"(c[0]), "+f"(c[1]), "+f"(c[2]), "+f"(c[3])
        : "r"(a[0]), "r"(a[1]), "r"(a[2]), "r"(a[3]), "r"(b0), "r"(b1));
}
__device__ __forceinline__ float warp_sum(float v) {
#pragma unroll
    for (int o = 16; o; o >>= 1) v += __shfl_xor_sync(0xffffffffu, v, o);
    return v;
}

// ---------------- one-pass padded-CSR fill ---------------------------------
__global__ void k_fillpad(const int* __restrict__ src, const int* __restrict__ tgt,
                          int e) {
    int i = (blockIdx.x * blockDim.x + threadIdx.x) * 2;
    if (i + 1 < e) {
        int2 s = *(const int2*)&src[i];
        int2 t = *(const int2*)&tgt[i];
        int p0 = atomicAdd(&g_cursor[t.x], 1);
        if (p0 < CAP) g_pad[(size_t)t.x * CAP + p0] = s.x;
        int p1 = atomicAdd(&g_cursor[t.y], 1);
        if (p1 < CAP) g_pad[(size_t)t.y * CAP + p1] = s.y;
    } else if (i < e) {
        int s = src[i], t = tgt[i];
        int p = atomicAdd(&g_cursor[t], 1);
        if (p < CAP) g_pad[(size_t)t * CAP + p] = s;
    }
}

// ---------------- layer-0: aggregate RAW 11-wide features ------------------
__global__ void k_agg_feat(const float* __restrict__ X, float* __restrict__ out, int n) {
    int g = threadIdx.x >> 4, f = threadIdx.x & 15;
    int node = blockIdx.x * 16 + g;
    if (node >= n) return;
    int deg = g_cursor[node];
    int rs = node * CAP, re = rs + deg;
    float acc = 0.f;
    for (int base = rs; base < re; base += 16) {
        int idx = base + f;
        int s = (idx < re) ? g_pad[idx] : 0;
#pragma unroll
        for (int j = 0; j < 16; j++) {
            int sj = __shfl_sync(0xffffffffu, s, j, 16);
            if (base + j < re && f < 11) acc += X[sj * 11 + f];
        }
    }
    float inv = 1.0f / (float)max(deg, 1);
    if (f < 11) out[node * 16 + f] = acc * inv;
}

// ---------------- fused 11->128 GEMM + LN + ReLU -> fp16 (+weight cvt) -----
__global__ void __launch_bounds__(256) k_gemm0_ln(const float* __restrict__ AF,
                                                  const float* __restrict__ W,
                                                  const float* __restrict__ b,
                                                  const float* __restrict__ gam,
                                                  const float* __restrict__ bet,
                                                  const float* __restrict__ W1,
                                                  const float* __restrict__ W2,
                                                  __half2* __restrict__ Yh, int n) {
    // side job: fp32->fp16 weight conversion for the MMA layers
    if (blockIdx.x < 64) {
        int i = blockIdx.x * 256 + threadIdx.x;
        g_hW1[i] = __float2half(W1[i]);
    } else if (blockIdx.x < 96) {
        int i = (blockIdx.x - 64) * 256 + threadIdx.x;
        g_hW2[i] = __float2half(W2[i]);
    }

    __shared__ float sW[128 * 11];
    __shared__ float sb[128], sg[128], sbe[128];
    int tid = threadIdx.x;
    for (int i = tid; i < 128 * 11; i += 256) sW[i] = W[i];
    if (tid < 128) { sb[tid] = b[tid]; sg[tid] = gam[tid]; sbe[tid] = bet[tid]; }
    __syncthreads();
    int warp = tid >> 5, lane = tid & 31;
    int node = blockIdx.x * 8 + warp;
    if (node >= n) return;
    int deg = g_cursor[node];
    float f[11];
#pragma unroll
    for (int k = 0; k < 11; k++) f[k] = AF[node * 16 + k];
    int c0 = lane * 4;
    float a0 = sb[c0], a1 = sb[c0 + 1], a2 = sb[c0 + 2], a3 = sb[c0 + 3];
#pragma unroll
    for (int k = 0; k < 11; k++) {
        a0 += f[k] * sW[(c0 + 0) * 11 + k];
        a1 += f[k] * sW[(c0 + 1) * 11 + k];
        a2 += f[k] * sW[(c0 + 2) * 11 + k];
        a3 += f[k] * sW[(c0 + 3) * 11 + k];
    }
    if (deg == 0) { a0 = a1 = a2 = a3 = 0.f; }
    float mean = warp_sum(a0 + a1 + a2 + a3) * (1.0f / 128.0f);
    float d0 = a0 - mean, d1 = a1 - mean, d2 = a2 - mean, d3 = a3 - mean;
    float var = warp_sum(d0 * d0 + d1 * d1 + d2 * d2 + d3 * d3) * (1.0f / 128.0f);
    float rstd = rsqrtf(var + LN_EPS);
    float rx = fmaxf(d0 * rstd * sg[c0 + 0] + sbe[c0 + 0], 0.f);
    float ry = fmaxf(d1 * rstd * sg[c0 + 1] + sbe[c0 + 1], 0.f);
    float rz = fmaxf(d2 * rstd * sg[c0 + 2] + sbe[c0 + 2], 0.f);
    float rw = fmaxf(d3 * rstd * sg[c0 + 3] + sbe[c0 + 3], 0.f);
    __half2 h0 = __floats2half2_rn(rx, ry);
    __half2 h1 = __floats2half2_rn(rz, rw);
    uint2 u;
    u.x = *(unsigned*)&h0;
    u.y = *(unsigned*)&h1;
    *(uint2*)&Yh[(size_t)node * 64 + lane * 2] = u;
}

// ---------------- tensor-core GEMM: Yh[n][NT] = half(Xh * Wh^T + b) --------
template <int NT>
__global__ void __launch_bounds__(256, 2) k_mma(const __half* __restrict__ X,
                                                const __half* __restrict__ Wh,
                                                const float* __restrict__ bias,
                                                __half2* __restrict__ Yh, int n) {
    const int WN = NT / 2;
    __shared__ __half sx[128 * 72];
    __shared__ __half sw[NT * 72];
    int tid = threadIdx.x, lane = tid & 31, wid = tid >> 5;
    int wy = wid >> 1, wx = wid & 1;
    int mBase = blockIdx.x * 128;
    int r8 = lane & 7, sub = lane >> 3;
    unsigned sxb = smem_u32(sx), swb = smem_u32(sw);

    float c[2][WN / 8][4];
#pragma unroll
    for (int mi = 0; mi < 2; mi++)
#pragma unroll
        for (int nb = 0; nb < WN / 8; nb++)
#pragma unroll
            for (int q = 0; q < 4; q++) c[mi][nb][q] = 0.f;

    for (int kc = 0; kc < 128; kc += 64) {
#pragma unroll
        for (int it = 0; it < 4; it++) {
            int idx = tid + it * 256;
            int r = idx >> 3, c8 = idx & 7;
            int gm = mBase + r;
            uint4 v = make_uint4(0u, 0u, 0u, 0u);
            if (gm < n) v = ((const uint4*)X)[(size_t)gm * 16 + (kc >> 3) + c8];
            *(uint4*)&sx[r * 72 + c8 * 8] = v;
        }
#pragma unroll
        for (int it = 0; it < NT / 32; it++) {
            int idx = tid + it * 256;
            int r = idx >> 3, c8 = idx & 7;
            uint4 v = ((const uint4*)Wh)[r * 16 + (kc >> 3) + c8];
            *(uint4*)&sw[r * 72 + c8 * 8] = v;
        }
        __syncthreads();
#pragma unroll
        for (int ks = 0; ks < 4; ks++) {
            int k0 = ks * 16;
            unsigned a[2][4];
#pragma unroll
            for (int mi = 0; mi < 2; mi++) {
                int row = wy * 32 + mi * 16 + r8 + ((sub & 1) << 3);
                int kof = k0 + ((sub >> 1) << 3);
                ldmx4(a[mi], sxb + (row * 72 + kof) * 2);
            }
            unsigned bf[WN / 8][2];
#pragma unroll
            for (int nb = 0; nb < WN / 16; nb++) {
                int n0 = wx * WN + nb * 16;
                int row = n0 + r8 + ((sub >> 1) << 3);
                int kof = k0 + ((sub & 1) << 3);
                unsigned t4[4];
                ldmx4(t4, swb + (row * 72 + kof) * 2);
                bf[2 * nb][0] = t4[0];
                bf[2 * nb][1] = t4[1];
                bf[2 * nb + 1][0] = t4[2];
                bf[2 * nb + 1][1] = t4[3];
            }
#pragma unroll
            for (int mi = 0; mi < 2; mi++)
#pragma unroll
                for (int nb = 0; nb < WN / 8; nb++)
                    mma16816(c[mi][nb], a[mi], bf[nb][0], bf[nb][1]);
        }
        __syncthreads();
    }

    int g = lane >> 2, t = lane & 3;
#pragma unroll
    for (int mi = 0; mi < 2; mi++) {
        int row0 = mBase + wy * 32 + mi * 16 + g;
#pragma unroll
        for (int nb = 0; nb < WN / 8; nb++) {
            int col = wx * WN + nb * 8 + 2 * t;
            float2 bv = *(const float2*)&bias[col];
            if (row0 < n) {
                __half2 h = __floats2half2_rn(c[mi][nb][0] + bv.x, c[mi][nb][1] + bv.y);
                Yh[(size_t)row0 * (NT / 2) + (col >> 1)] = h;
            }
            int row1 = row0 + 8;
            if (row1 < n) {
                __half2 h = __floats2half2_rn(c[mi][nb][2] + bv.x, c[mi][nb][3] + bv.y);
                Yh[(size_t)row1 * (NT / 2) + (col >> 1)] = h;
            }
        }
    }
}

// ---------------- fused aggregate (fp16 in) + deg-norm + LN (+ReLU) --------
__device__ __forceinline__ void acc_row128(float* acc, const __half2* __restrict__ X,
                                           int s, int lane) {
    uint2 u = *(const uint2*)&X[(size_t)s * 64 + lane * 2];
    __half2 h0 = *(__half2*)&u.x, h1 = *(__half2*)&u.y;
    float2 f0 = __half22float2(h0), f1 = __half22float2(h1);
    acc[0] += f0.x; acc[1] += f0.y; acc[2] += f1.x; acc[3] += f1.y;
}

template <int HD, bool RELU, bool HOUT>
__global__ void k_agg_ln(const __half2* __restrict__ XT, const float* __restrict__ gam,
                         const float* __restrict__ bet, void* __restrict__ out, int n) {
    int gw = (blockIdx.x * blockDim.x + threadIdx.x) >> 5;
    int lane = threadIdx.x & 31;
    if (gw >= n) return;
    int deg = g_cursor[gw];
    int rs = gw * CAP, re = rs + deg;
    const int V = HD / 32;
    float acc[V];
#pragma unroll
    for (int i = 0; i < V; i++) acc[i] = 0.f;

    int e = rs;
    if constexpr (V == 4) {
        for (; e + 3 < re; e += 4) {
            int s0 = g_pad[e + 0], s1 = g_pad[e + 1];
            int s2 = g_pad[e + 2], s3 = g_pad[e + 3];
            acc_row128(acc, XT, s0, lane);
            acc_row128(acc, XT, s1, lane);
            acc_row128(acc, XT, s2, lane);
            acc_row128(acc, XT, s3, lane);
        }
        for (; e < re; e++) acc_row128(acc, XT, g_pad[e], lane);
    } else {
        for (; e + 3 < re; e += 4) {
            int s0 = g_pad[e + 0], s1 = g_pad[e + 1];
            int s2 = g_pad[e + 2], s3 = g_pad[e + 3];
            float2 f0 = __half22float2(XT[(size_t)s0 * 32 + lane]);
            float2 f1 = __half22float2(XT[(size_t)s1 * 32 + lane]);
            float2 f2 = __half22float2(XT[(size_t)s2 * 32 + lane]);
            float2 f3 = __half22float2(XT[(size_t)s3 * 32 + lane]);
            acc[0] += (f0.x + f1.x) + (f2.x + f3.x);
            acc[1] += (f0.y + f1.y) + (f2.y + f3.y);
        }
        for (; e < re; e++) {
            float2 f0 = __half22float2(XT[(size_t)g_pad[e] * 32 + lane]);
            acc[0] += f0.x; acc[1] += f0.y;
        }
    }

    float inv = 1.0f / (float)(deg > 0 ? deg : 1);
    float v[V];
    float psum = 0.f;
#pragma unroll
    for (int i = 0; i < V; i++) { v[i] = acc[i] * inv; psum += v[i]; }
    float mean = warp_sum(psum) * (1.0f / (float)HD);
    float d[V];
    float ps2 = 0.f;
#pragma unroll
    for (int i = 0; i < V; i++) { d[i] = v[i] - mean; ps2 += d[i] * d[i]; }
    float var = warp_sum(ps2) * (1.0f / (float)HD);
    float rstd = rsqrtf(var + LN_EPS);

    if constexpr (V == 4) {
        float4 G = *(const float4*)&gam[lane * 4];
        float4 B = *(const float4*)&bet[lane * 4];
        float rx = d[0] * rstd * G.x + B.x;
        float ry = d[1] * rstd * G.y + B.y;
        float rz = d[2] * rstd * G.z + B.z;
        float rw = d[3] * rstd * G.w + B.w;
        if (RELU) {
            rx = fmaxf(rx, 0.f); ry = fmaxf(ry, 0.f);
            rz = fmaxf(rz, 0.f); rw = fmaxf(rw, 0.f);
        }
        if constexpr (HOUT) {
            __half2 h0 = __floats2half2_rn(rx, ry);
            __half2 h1 = __floats2half2_rn(rz, rw);
            uint2 u;
            u.x = *(unsigned*)&h0;
            u.y = *(unsigned*)&h1;
            *(uint2*)&((__half2*)out)[(size_t)gw * 64 + lane * 2] = u;
        } else {
            float4 r = make_float4(rx, ry, rz, rw);
            *(float4*)&((float*)out)[(size_t)gw * HD + lane * 4] = r;
        }
    } else {
        float2 G = *(const float2*)&gam[lane * 2];
        float2 B = *(const float2*)&bet[lane * 2];
        float2 r;
        r.x = d[0] * rstd * G.x + B.x;
        r.y = d[1] * rstd * G.y + B.y;
        if (RELU) { r.x = fmaxf(r.x, 0.f); r.y = fmaxf(r.y, 0.f); }
        *(float2*)&((float*)out)[(size_t)gw * HD + lane * 2] = r;
    }
}

// ---------------- launcher -------------------------------------------------
extern "C" void kernel_launch(void* const* d_in, const int* in_sizes, int n_in,
                              void* d_out, int out_size) {
    const float* nf  = (const float*)d_in[0];
    const int*   ei  = (const int*)d_in[1];
    const float* W0  = (const float*)d_in[2];
    const float* b0  = (const float*)d_in[3];
    const float* W1  = (const float*)d_in[4];
    const float* b1  = (const float*)d_in[5];
    const float* W2  = (const float*)d_in[6];
    const float* b2  = (const float*)d_in[7];
    const float* g0  = (const float*)d_in[8];
    const float* be0 = (const float*)d_in[9];
    const float* g1  = (const float*)d_in[10];
    const float* be1 = (const float*)d_in[11];
    const float* g2  = (const float*)d_in[12];
    const float* be2 = (const float*)d_in[13];

    int n = in_sizes[0] / 11;
    int e = in_sizes[1] / 2;
    const int* src = ei;
    const int* tgt = ei + e;

    float* bufA;
    __half2 *hX, *hY;
    __half *hW1, *hW2;
    int* curp;
    cudaGetSymbolAddress((void**)&bufA, g_buf_a);
    cudaGetSymbolAddress((void**)&hX, g_hx);
    cudaGetSymbolAddress((void**)&hY, g_hy);
    cudaGetSymbolAddress((void**)&hW1, g_hW1);
    cudaGetSymbolAddress((void**)&hW2, g_hW2);
    cudaGetSymbolAddress((void**)&curp, g_cursor);

    // one-pass padded-CSR build
    cudaMemsetAsync(curp, 0, n * sizeof(int));
    k_fillpad<<<(e / 2 + 255) / 256, 256>>>(src, tgt, e);

    // layer 0 (k_gemm0_ln also converts W1/W2 to fp16 as a side job)
    k_agg_feat<<<(n + 15) / 16, 256>>>(nf, bufA, n);
    k_gemm0_ln<<<(n + 7) / 8, 256>>>(bufA, W0, b0, g0, be0, W1, W2, hX, n);

    // layer 1: 128 -> 128 (tensor cores)
    k_mma<128><<<(n + 127) / 128, 256>>>((const __half*)hX, hW1, b1, hY, n);
    k_agg_ln<128, true, true><<<(n + 7) / 8, 256>>>(hY, g1, be1, hX, n);

    // layer 2: 128 -> 64 (tensor cores)
    k_mma<64><<<(n + 127) / 128, 256>>>((const __half*)hX, hW2, b2, hY, n);
    k_agg_ln<64, false, false><<<(n + 7) / 8, 256>>>(hY, g2, be2, d_out, n);
}

// round 8
// speedup vs baseline: 2.6440x; 1.0204x over previous
#include <cuda_runtime.h>
#include <cuda_fp16.h>

#define NMAX 100000
#define EMAX 1600000
#define CAP 96
#define LN_EPS 1e-5f

// ---------------- scratch (device globals: no allocation allowed) ----------
__device__ int   g_cursor[NMAX];
__device__ int   g_pad[(size_t)NMAX * CAP];           // padded adjacency (src ids)
__device__ __half g_xf[(size_t)NMAX * 16];            // fp16 padded node features
__device__ __half2 g_hx[(size_t)NMAX * 64];           // GEMM input activations
__device__ __half2 g_hy[(size_t)NMAX * 64];           // GEMM output / gather operand
__device__ __half  g_hW1[128 * 128];
__device__ __half  g_hW2[64 * 128];

// ---------------- helpers --------------------------------------------------
__device__ __forceinline__ unsigned smem_u32(const void* p) {
    unsigned a;
    asm("{ .reg .u64 t; cvta.to.shared.u64 t, %1; cvt.u32.u64 %0, t; }"
        : "=r"(a) : "l"(p));
    return a;
}
__device__ __forceinline__ void ldmx4(unsigned* r, unsigned addr) {
    asm volatile("ldmatrix.sync.aligned.m8n8.x4.shared.b16 {%0,%1,%2,%3}, [%4];"
                 : "=r"(r[0]), "=r"(r[1]), "=r"(r[2]), "=r"(r[3]) : "r"(addr));
}
__device__ __forceinline__ void mma16816(float* c, const unsigned* a, unsigned b0,
                                         unsigned b1) {
    asm volatile(
        "mma.sync.aligned.m16n8k16.row.col.f32.f16.f16.f32 "
        "{%0,%1,%2,%3},{%4,%5,%6,%7},{%8,%9},{%0,%1,%2,%3};"
        : "+f"(c[0]), "+f"(c[1]), "+f"(c[2]), "+f"(c[3])
        : "r"(a[0]), "r"(a[1]), "r"(a[2]), "r"(a[3]), "r"(b0), "r"(b1));
}
__device__ __forceinline__ void cpa16(unsigned dst, const void* src, bool valid) {
    int sz = valid ? 16 : 0;
    asm volatile("cp.async.cg.shared.global [%0], [%1], 16, %2;"
                 :: "r"(dst), "l"(src), "r"(sz));
}
__device__ __forceinline__ void cpa_wait_all() {
    asm volatile("cp.async.commit_group;");
    asm volatile("cp.async.wait_group 0;");
}
__device__ __forceinline__ float warp_sum(float v) {
#pragma unroll
    for (int o = 16; o; o >>= 1) v += __shfl_xor_sync(0xffffffffu, v, o);
    return v;
}

// ---------------- feature fp32 -> fp16 padded [N,16] -----------------------
__global__ void k_cvtX(const float* __restrict__ X, int n) {
    int i = blockIdx.x * 256 + threadIdx.x;
    if (i >= n) return;
    float v[16];
#pragma unroll
    for (int k = 0; k < 11; k++) v[k] = X[i * 11 + k];
#pragma unroll
    for (int k = 11; k < 16; k++) v[k] = 0.f;
    __half2 h[8];
#pragma unroll
    for (int k = 0; k < 8; k++) h[k] = __floats2half2_rn(v[2 * k], v[2 * k + 1]);
    uint4* o = (uint4*)&g_xf[(size_t)i * 16];
    o[0] = *(uint4*)&h[0];
    o[1] = *(uint4*)&h[4];
}

// ---------------- one-pass padded-CSR fill (4 edges/thread) ----------------
__global__ void k_fillpad(const int* __restrict__ src, const int* __restrict__ tgt,
                          int e) {
    int i = (blockIdx.x * blockDim.x + threadIdx.x) * 4;
    if (i + 3 < e) {
        int4 s = *(const int4*)&src[i];
        int4 t = *(const int4*)&tgt[i];
        int p0 = atomicAdd(&g_cursor[t.x], 1);
        if (p0 < CAP) g_pad[(size_t)t.x * CAP + p0] = s.x;
        int p1 = atomicAdd(&g_cursor[t.y], 1);
        if (p1 < CAP) g_pad[(size_t)t.y * CAP + p1] = s.y;
        int p2 = atomicAdd(&g_cursor[t.z], 1);
        if (p2 < CAP) g_pad[(size_t)t.z * CAP + p2] = s.z;
        int p3 = atomicAdd(&g_cursor[t.w], 1);
        if (p3 < CAP) g_pad[(size_t)t.w * CAP + p3] = s.w;
    } else {
        for (int k = i; k < e; k++) {
            int s = src[k], t = tgt[k];
            int p = atomicAdd(&g_cursor[t], 1);
            if (p < CAP) g_pad[(size_t)t * CAP + p] = s;
        }
    }
}

// ---------------- fused layer-0: gather + 11->128 GEMV + LN + ReLU ---------
// warp per node; lanes split into 2 groups of 16, group g takes edges rs+2j+g,
// lane f (0..15) accumulates feature f from fp16 padded features.
__global__ void __launch_bounds__(256) k_l0(const float* __restrict__ W,
                                            const float* __restrict__ b,
                                            const float* __restrict__ gam,
                                            const float* __restrict__ bet,
                                            const float* __restrict__ W1,
                                            const float* __restrict__ W2,
                                            __half2* __restrict__ Yh, int n) {
    // side job: fp32->fp16 weight conversion for the MMA layers
    if (blockIdx.x < 64) {
        int i = blockIdx.x * 256 + threadIdx.x;
        g_hW1[i] = __float2half(W1[i]);
    } else if (blockIdx.x < 96) {
        int i = (blockIdx.x - 64) * 256 + threadIdx.x;
        g_hW2[i] = __float2half(W2[i]);
    }

    __shared__ float sW[128 * 11];
    __shared__ float sb[128], sg[128], sbe[128];
    int tid = threadIdx.x;
    for (int i = tid; i < 128 * 11; i += 256) sW[i] = W[i];
    if (tid < 128) { sb[tid] = b[tid]; sg[tid] = gam[tid]; sbe[tid] = bet[tid]; }
    __syncthreads();

    int warp = tid >> 5, lane = tid & 31;
    int node = blockIdx.x * 8 + warp;
    if (node >= n) return;
    int deg = g_cursor[node];
    int half = lane >> 4, f = lane & 15;
    int base = node * CAP;

    float acc = 0.f;
    for (int j = half; j < deg; j += 2) {
        int s = g_pad[base + j];
        acc += __half2float(g_xf[(size_t)s * 16 + f]);
    }
    acc += __shfl_xor_sync(0xffffffffu, acc, 16);
    float inv = 1.0f / (float)max(deg, 1);

    float fk[11];
#pragma unroll
    for (int k = 0; k < 11; k++)
        fk[k] = __shfl_sync(0xffffffffu, acc, k) * inv;

    int c0 = lane * 4;
    float a0 = sb[c0], a1 = sb[c0 + 1], a2 = sb[c0 + 2], a3 = sb[c0 + 3];
#pragma unroll
    for (int k = 0; k < 11; k++) {
        a0 += fk[k] * sW[(c0 + 0) * 11 + k];
        a1 += fk[k] * sW[(c0 + 1) * 11 + k];
        a2 += fk[k] * sW[(c0 + 2) * 11 + k];
        a3 += fk[k] * sW[(c0 + 3) * 11 + k];
    }
    if (deg == 0) { a0 = a1 = a2 = a3 = 0.f; }
    float mean = warp_sum(a0 + a1 + a2 + a3) * (1.0f / 128.0f);
    float d0 = a0 - mean, d1 = a1 - mean, d2 = a2 - mean, d3 = a3 - mean;
    float var = warp_sum(d0 * d0 + d1 * d1 + d2 * d2 + d3 * d3) * (1.0f / 128.0f);
    float rstd = rsqrtf(var + LN_EPS);
    float rx = fmaxf(d0 * rstd * sg[c0 + 0] + sbe[c0 + 0], 0.f);
    float ry = fmaxf(d1 * rstd * sg[c0 + 1] + sbe[c0 + 1], 0.f);
    float rz = fmaxf(d2 * rstd * sg[c0 + 2] + sbe[c0 + 2], 0.f);
    float rw = fmaxf(d3 * rstd * sg[c0 + 3] + sbe[c0 + 3], 0.f);
    __half2 h0 = __floats2half2_rn(rx, ry);
    __half2 h1 = __floats2half2_rn(rz, rw);
    uint2 u;
    u.x = *(unsigned*)&h0;
    u.y = *(unsigned*)&h1;
    *(uint2*)&Yh[(size_t)node * 64 + lane * 2] = u;
}

// ---------------- tensor-core GEMM v2: single-stage full-K, cp.async -------
// smem stride 136 halfs (272B): +16B bank shift per row -> ldmatrix
// conflict-free. Whole K=128 staged at once (MLP=8/thread), one sync.
template <int NT>
__global__ void __launch_bounds__(256, 2) k_mma(const __half* __restrict__ X,
                                                const __half* __restrict__ Wh,
                                                const float* __restrict__ bias,
                                                __half2* __restrict__ Yh, int n) {
    const int WN = NT / 2;
    const int STR = 136;
    extern __shared__ __half dsm[];
    __half* sx = dsm;                 // 128 x STR
    __half* sw = dsm + 128 * STR;     // NT x STR
    int tid = threadIdx.x, lane = tid & 31, wid = tid >> 5;
    int wy = wid >> 1, wx = wid & 1;
    int mBase = blockIdx.x * 128;
    int r8 = lane & 7, sub = lane >> 3;
    unsigned sxb = smem_u32(sx), swb = smem_u32(sw);

    // stage X: 128 rows x 16 uint4 = 2048 copies over 256 threads
#pragma unroll
    for (int it = 0; it < 8; it++) {
        int idx = tid + it * 256;
        int r = idx >> 4, c16 = idx & 15;
        int gm = mBase + r;
        cpa16(sxb + (r * STR + c16 * 8) * 2,
              &X[(size_t)gm * 128 + c16 * 8], gm < n);
    }
    // stage W: NT rows x 16 uint4
#pragma unroll
    for (int it = 0; it < NT / 16; it++) {
        int idx = tid + it * 256;
        int r = idx >> 4, c16 = idx & 15;
        cpa16(swb + (r * STR + c16 * 8) * 2, &Wh[r * 128 + c16 * 8], true);
    }
    cpa_wait_all();
    __syncthreads();

    float c[2][WN / 8][4];
#pragma unroll
    for (int mi = 0; mi < 2; mi++)
#pragma unroll
        for (int nb = 0; nb < WN / 8; nb++)
#pragma unroll
            for (int q = 0; q < 4; q++) c[mi][nb][q] = 0.f;

#pragma unroll
    for (int ks = 0; ks < 8; ks++) {
        int k0 = ks * 16;
        unsigned a[2][4];
#pragma unroll
        for (int mi = 0; mi < 2; mi++) {
            int row = wy * 32 + mi * 16 + r8 + ((sub & 1) << 3);
            int kof = k0 + ((sub >> 1) << 3);
            ldmx4(a[mi], sxb + (row * STR + kof) * 2);
        }
        unsigned bf[WN / 8][2];
#pragma unroll
        for (int nb = 0; nb < WN / 16; nb++) {
            int n0 = wx * WN + nb * 16;
            int row = n0 + r8 + ((sub >> 1) << 3);
            int kof = k0 + ((sub & 1) << 3);
            unsigned t4[4];
            ldmx4(t4, swb + (row * STR + kof) * 2);
            bf[2 * nb][0] = t4[0];
            bf[2 * nb][1] = t4[1];
            bf[2 * nb + 1][0] = t4[2];
            bf[2 * nb + 1][1] = t4[3];
        }
#pragma unroll
        for (int mi = 0; mi < 2; mi++)
#pragma unroll
            for (int nb = 0; nb < WN / 8; nb++)
                mma16816(c[mi][nb], a[mi], bf[nb][0], bf[nb][1]);
    }

    int g = lane >> 2, t = lane & 3;
#pragma unroll
    for (int mi = 0; mi < 2; mi++) {
        int row0 = mBase + wy * 32 + mi * 16 + g;
#pragma unroll
        for (int nb = 0; nb < WN / 8; nb++) {
            int col = wx * WN + nb * 8 + 2 * t;
            float2 bv = *(const float2*)&bias[col];
            if (row0 < n) {
                __half2 h = __floats2half2_rn(c[mi][nb][0] + bv.x, c[mi][nb][1] + bv.y);
                Yh[(size_t)row0 * (NT / 2) + (col >> 1)] = h;
            }
            int row1 = row0 + 8;
            if (row1 < n) {
                __half2 h = __floats2half2_rn(c[mi][nb][2] + bv.x, c[mi][nb][3] + bv.y);
                Yh[(size_t)row1 * (NT / 2) + (col >> 1)] = h;
            }
        }
    }
}

// ---------------- fused aggregate (fp16 in) + deg-norm + LN (+ReLU) --------
__device__ __forceinline__ void acc_row128(float* acc, const __half2* __restrict__ X,
                                           int s, int lane) {
    uint2 u = *(const uint2*)&X[(size_t)s * 64 + lane * 2];
    __half2 h0 = *(__half2*)&u.x, h1 = *(__half2*)&u.y;
    float2 f0 = __half22float2(h0), f1 = __half22float2(h1);
    acc[0] += f0.x; acc[1] += f0.y; acc[2] += f1.x; acc[3] += f1.y;
}

template <int HD, bool RELU, bool HOUT>
__global__ void k_agg_ln(const __half2* __restrict__ XT, const float* __restrict__ gam,
                         const float* __restrict__ bet, void* __restrict__ out, int n) {
    int gw = (blockIdx.x * blockDim.x + threadIdx.x) >> 5;
    int lane = threadIdx.x & 31;
    if (gw >= n) return;
    int deg = g_cursor[gw];
    int rs = gw * CAP, re = rs + deg;
    const int V = HD / 32;
    float acc[V];
#pragma unroll
    for (int i = 0; i < V; i++) acc[i] = 0.f;

    int e = rs;
    if constexpr (V == 4) {
        for (; e + 3 < re; e += 4) {
            int s0 = g_pad[e + 0], s1 = g_pad[e + 1];
            int s2 = g_pad[e + 2], s3 = g_pad[e + 3];
            acc_row128(acc, XT, s0, lane);
            acc_row128(acc, XT, s1, lane);
            acc_row128(acc, XT, s2, lane);
            acc_row128(acc, XT, s3, lane);
        }
        for (; e < re; e++) acc_row128(acc, XT, g_pad[e], lane);
    } else {
        for (; e + 3 < re; e += 4) {
            int s0 = g_pad[e + 0], s1 = g_pad[e + 1];
            int s2 = g_pad[e + 2], s3 = g_pad[e + 3];
            float2 f0 = __half22float2(XT[(size_t)s0 * 32 + lane]);
            float2 f1 = __half22float2(XT[(size_t)s1 * 32 + lane]);
            float2 f2 = __half22float2(XT[(size_t)s2 * 32 + lane]);
            float2 f3 = __half22float2(XT[(size_t)s3 * 32 + lane]);
            acc[0] += (f0.x + f1.x) + (f2.x + f3.x);
            acc[1] += (f0.y + f1.y) + (f2.y + f3.y);
        }
        for (; e < re; e++) {
            float2 f0 = __half22float2(XT[(size_t)g_pad[e] * 32 + lane]);
            acc[0] += f0.x; acc[1] += f0.y;
        }
    }

    float inv = 1.0f / (float)(deg > 0 ? deg : 1);
    float v[V];
    float psum = 0.f;
#pragma unroll
    for (int i = 0; i < V; i++) { v[i] = acc[i] * inv; psum += v[i]; }
    float mean = warp_sum(psum) * (1.0f / (float)HD);
    float d[V];
    float ps2 = 0.f;
#pragma unroll
    for (int i = 0; i < V; i++) { d[i] = v[i] - mean; ps2 += d[i] * d[i]; }
    float var = warp_sum(ps2) * (1.0f / (float)HD);
    float rstd = rsqrtf(var + LN_EPS);

    if constexpr (V == 4) {
        float4 G = *(const float4*)&gam[lane * 4];
        float4 B = *(const float4*)&bet[lane * 4];
        float rx = d[0] * rstd * G.x + B.x;
        float ry = d[1] * rstd * G.y + B.y;
        float rz = d[2] * rstd * G.z + B.z;
        float rw = d[3] * rstd * G.w + B.w;
        if (RELU) {
            rx = fmaxf(rx, 0.f); ry = fmaxf(ry, 0.f);
            rz = fmaxf(rz, 0.f); rw = fmaxf(rw, 0.f);
        }
        if constexpr (HOUT) {
            __half2 h0 = __floats2half2_rn(rx, ry);
            __half2 h1 = __floats2half2_rn(rz, rw);
            uint2 u;
            u.x = *(unsigned*)&h0;
            u.y = *(unsigned*)&h1;
            *(uint2*)&((__half2*)out)[(size_t)gw * 64 + lane * 2] = u;
        } else {
            float4 r = make_float4(rx, ry, rz, rw);
            *(float4*)&((float*)out)[(size_t)gw * HD + lane * 4] = r;
        }
    } else {
        float2 G = *(const float2*)&gam[lane * 2];
        float2 B = *(const float2*)&bet[lane * 2];
        float2 r;
        r.x = d[0] * rstd * G.x + B.x;
        r.y = d[1] * rstd * G.y + B.y;
        if (RELU) { r.x = fmaxf(r.x, 0.f); r.y = fmaxf(r.y, 0.f); }
        *(float2*)&((float*)out)[(size_t)gw * HD + lane * 2] = r;
    }
}

// ---------------- launcher -------------------------------------------------
extern "C" void kernel_launch(void* const* d_in, const int* in_sizes, int n_in,
                              void* d_out, int out_size) {
    const float* nf  = (const float*)d_in[0];
    const int*   ei  = (const int*)d_in[1];
    const float* W0  = (const float*)d_in[2];
    const float* b0  = (const float*)d_in[3];
    const float* W1  = (const float*)d_in[4];
    const float* b1  = (const float*)d_in[5];
    const float* W2  = (const float*)d_in[6];
    const float* b2  = (const float*)d_in[7];
    const float* g0  = (const float*)d_in[8];
    const float* be0 = (const float*)d_in[9];
    const float* g1  = (const float*)d_in[10];
    const float* be1 = (const float*)d_in[11];
    const float* g2  = (const float*)d_in[12];
    const float* be2 = (const float*)d_in[13];

    int n = in_sizes[0] / 11;
    int e = in_sizes[1] / 2;
    const int* src = ei;
    const int* tgt = ei + e;

    __half2 *hX, *hY;
    __half *hW1, *hW2;
    int* curp;
    cudaGetSymbolAddress((void**)&hX, g_hx);
    cudaGetSymbolAddress((void**)&hY, g_hy);
    cudaGetSymbolAddress((void**)&hW1, g_hW1);
    cudaGetSymbolAddress((void**)&hW2, g_hW2);
    cudaGetSymbolAddress((void**)&curp, g_cursor);

    const int SMEM128 = (128 + 128) * 136 * 2;   // 69632
    const int SMEM64  = (128 + 64) * 136 * 2;    // 52224
    cudaFuncSetAttribute(k_mma<128>, cudaFuncAttributeMaxDynamicSharedMemorySize,
                         SMEM128);
    cudaFuncSetAttribute(k_mma<64>, cudaFuncAttributeMaxDynamicSharedMemorySize,
                         SMEM64);

    // padded-CSR build + feature conversion
    cudaMemsetAsync(curp, 0, n * sizeof(int));
    k_cvtX<<<(n + 255) / 256, 256>>>(nf, n);
    k_fillpad<<<(e / 4 + 255) / 256, 256>>>(src, tgt, e);

    // layer 0: fused gather + GEMV + LN + ReLU (also converts W1/W2 to fp16)
    k_l0<<<(n + 7) / 8, 256>>>(W0, b0, g0, be0, W1, W2, hX, n);

    // layer 1: 128 -> 128 (tensor cores)
    k_mma<128><<<(n + 127) / 128, 256, SMEM128>>>((const __half*)hX, hW1, b1, hY, n);
    k_agg_ln<128, true, true><<<(n + 7) / 8, 256>>>(hY, g1, be1, hX, n);

    // layer 2: 128 -> 64 (tensor cores)
    k_mma<64><<<(n + 127) / 128, 256, SMEM64>>>((const __half*)hX, hW2, b2, hY, n);
    k_agg_ln<64, false, false><<<(n + 7) / 8, 256>>>(hY, g2, be2, d_out, n);
}